// round 2
// baseline (speedup 1.0000x reference)
#include <cuda_runtime.h>
#include <math.h>

#define BATCH   2
#define L_SEQ   2048
#define DIM     1024
#define HEADS   16
#define DH      64
#define QKV_COLS 3072
#define PHI_F   1.6180339887498949f

// Scratch (device globals: allocation-free rule)
__device__ float g_qkv[(size_t)BATCH * L_SEQ * QKV_COLS];  // ~50 MB
__device__ float g_att[(size_t)BATCH * L_SEQ * DIM];       // ~17 MB

// ---------------------------------------------------------------------------
// SGEMM: C[M,N] = A[M,K] @ B[K,N] (+ optional bias[N])
// 128x128 block tile, BK=8, 256 threads, 8x8 per-thread microtile.
// Assumes M%128==0, N%128==0, K%8==0 (true for all our shapes).
// ---------------------------------------------------------------------------
__global__ __launch_bounds__(256) void sgemm_kernel(
    const float* __restrict__ A, const float* __restrict__ B,
    float* __restrict__ C, int M, int N, int K,
    const float* __restrict__ bias)
{
    __shared__ float As[8][128];
    __shared__ float Bs[8][128];

    const int tid  = threadIdx.x;
    const int arow = tid >> 1;            // 0..127
    const int acol = (tid & 1) << 2;      // 0 or 4
    const int brow = tid >> 5;            // 0..7
    const int bcol = (tid & 31) << 2;     // 0..124
    const int ty = tid >> 4;              // 0..15
    const int tx = tid & 15;              // 0..15

    const float* Ab = A + (size_t)(blockIdx.y * 128) * K;
    const float* Bb = B + blockIdx.x * 128;

    float acc[8][8];
#pragma unroll
    for (int i = 0; i < 8; i++)
#pragma unroll
        for (int j = 0; j < 8; j++) acc[i][j] = 0.0f;

    for (int k0 = 0; k0 < K; k0 += 8) {
        float4 av = *(const float4*)(Ab + (size_t)arow * K + k0 + acol);
        As[acol + 0][arow] = av.x;
        As[acol + 1][arow] = av.y;
        As[acol + 2][arow] = av.z;
        As[acol + 3][arow] = av.w;
        float4 bv = *(const float4*)(Bb + (size_t)(k0 + brow) * N + bcol);
        *(float4*)&Bs[brow][bcol] = bv;
        __syncthreads();

#pragma unroll
        for (int kk = 0; kk < 8; kk++) {
            float a[8], b[8];
            *(float4*)(a)     = *(const float4*)&As[kk][ty * 8];
            *(float4*)(a + 4) = *(const float4*)&As[kk][ty * 8 + 4];
            *(float4*)(b)     = *(const float4*)&Bs[kk][tx * 8];
            *(float4*)(b + 4) = *(const float4*)&Bs[kk][tx * 8 + 4];
#pragma unroll
            for (int i = 0; i < 8; i++)
#pragma unroll
                for (int j = 0; j < 8; j++)
                    acc[i][j] = fmaf(a[i], b[j], acc[i][j]);
        }
        __syncthreads();
    }

    const int crow0 = blockIdx.y * 128 + ty * 8;
    const int ccol0 = blockIdx.x * 128 + tx * 8;
#pragma unroll
    for (int i = 0; i < 8; i++) {
        float v[8];
#pragma unroll
        for (int j = 0; j < 8; j++) {
            v[j] = acc[i][j];
            if (bias) v[j] += bias[ccol0 + j];
        }
        float* cp = C + (size_t)(crow0 + i) * N + ccol0;
        *(float4*)(cp)     = *(float4*)(v);
        *(float4*)(cp + 4) = *(float4*)(v + 4);
    }
}

// ---------------------------------------------------------------------------
// Flash attention, fp32. Grid: (L/64, HEADS, BATCH). Block: 256 threads.
// BM=BN=64, Dh=64. Q,V smem natural [64][64]; K (reused as P) padded [64][65].
// bias(i,j) = log(exp(-|pi-pj|)+1e-8) == -|pi-pj| to within 2.7e-8 absolute.
// ---------------------------------------------------------------------------
#define KP_STRIDE 65
#define FLASH_SMEM ((64 * 64 + 64 * KP_STRIDE + 64 * 64) * 4)

__global__ __launch_bounds__(256) void flash_kernel()
{
    extern __shared__ float sm[];
    float* Qs = sm;                       // [64][64]
    float* KP = sm + 64 * 64;             // [64][65]  K tile, reused as P
    float* Vs = KP + 64 * KP_STRIDE;      // [64][64]

    const int qt = blockIdx.x;
    const int h  = blockIdx.y;
    const int b  = blockIdx.z;
    const int tid = threadIdx.x;
    const int ty = tid >> 4, tx = tid & 15;
    const int r0 = ty * 4, c0 = tx * 4;

    const float* qbase = g_qkv + (size_t)b * L_SEQ * QKV_COLS + h * DH;
    const float* kbase = qbase + DIM;
    const float* vbase = qbase + 2 * DIM;

    // Load Q tile (rows qt*64 .. +63)
    for (int i = tid; i < 64 * 16; i += 256) {
        int row = i >> 4;
        int d4  = (i & 15) << 2;
        float4 v = *(const float4*)(qbase + (size_t)(qt * 64 + row) * QKV_COLS + d4);
        *(float4*)&Qs[row * 64 + d4] = v;
    }

    float m[4], lsum[4], o[4][4];
    float pq[4];
#pragma unroll
    for (int i = 0; i < 4; i++) {
        m[i] = -1e30f;
        lsum[i] = 0.0f;
#pragma unroll
        for (int j = 0; j < 4; j++) o[i][j] = 0.0f;
        int qi = qt * 64 + r0 + i;
        pq[i] = fmodf((float)qi * PHI_F, 1.0f);
    }
    __syncthreads();

    for (int kt = 0; kt < L_SEQ / 64; kt++) {
        // Load K (into KP, padded) and V tiles
        for (int i = tid; i < 64 * 16; i += 256) {
            int row = i >> 4;
            int d4  = (i & 15) << 2;
            float4 kv = *(const float4*)(kbase + (size_t)(kt * 64 + row) * QKV_COLS + d4);
            KP[row * KP_STRIDE + d4 + 0] = kv.x;
            KP[row * KP_STRIDE + d4 + 1] = kv.y;
            KP[row * KP_STRIDE + d4 + 2] = kv.z;
            KP[row * KP_STRIDE + d4 + 3] = kv.w;
            float4 vv = *(const float4*)(vbase + (size_t)(kt * 64 + row) * QKV_COLS + d4);
            *(float4*)&Vs[row * 64 + d4] = vv;
        }
        __syncthreads();

        // S = Q K^T (4x4 microtile)
        float s[4][4];
#pragma unroll
        for (int i = 0; i < 4; i++)
#pragma unroll
            for (int j = 0; j < 4; j++) s[i][j] = 0.0f;

#pragma unroll 8
        for (int kk = 0; kk < 64; kk++) {
            float qv[4], kv[4];
#pragma unroll
            for (int i = 0; i < 4; i++) qv[i] = Qs[(r0 + i) * 64 + kk];
#pragma unroll
            for (int j = 0; j < 4; j++) kv[j] = KP[(c0 + j) * KP_STRIDE + kk];
#pragma unroll
            for (int i = 0; i < 4; i++)
#pragma unroll
                for (int j = 0; j < 4; j++) s[i][j] = fmaf(qv[i], kv[j], s[i][j]);
        }

        // scale + phi bias
        float pk[4];
#pragma unroll
        for (int j = 0; j < 4; j++) {
            int kj = kt * 64 + c0 + j;
            pk[j] = fmodf((float)kj * PHI_F, 1.0f);
        }
#pragma unroll
        for (int i = 0; i < 4; i++)
#pragma unroll
            for (int j = 0; j < 4; j++)
                s[i][j] = s[i][j] * 0.125f - fabsf(pq[i] - pk[j]);

        __syncthreads();   // all threads done reading K before P overwrites it

        // online softmax; write P into KP buffer
#pragma unroll
        for (int i = 0; i < 4; i++) {
            float mx = fmaxf(fmaxf(s[i][0], s[i][1]), fmaxf(s[i][2], s[i][3]));
#pragma unroll
            for (int off = 8; off >= 1; off >>= 1)
                mx = fmaxf(mx, __shfl_xor_sync(0xffffffffu, mx, off));
            float mnew = fmaxf(m[i], mx);
            float corr = __expf(m[i] - mnew);
            float p[4];
            float rs = 0.0f;
#pragma unroll
            for (int j = 0; j < 4; j++) {
                p[j] = __expf(s[i][j] - mnew);
                rs += p[j];
            }
#pragma unroll
            for (int off = 8; off >= 1; off >>= 1)
                rs += __shfl_xor_sync(0xffffffffu, rs, off);
            lsum[i] = lsum[i] * corr + rs;
            m[i] = mnew;
#pragma unroll
            for (int j = 0; j < 4; j++) {
                o[i][j] *= corr;
                KP[(r0 + i) * KP_STRIDE + c0 + j] = p[j];
            }
        }
        __syncthreads();   // P visible

        // O += P @ V
#pragma unroll 8
        for (int kk = 0; kk < 64; kk++) {
            float pv[4], vv[4];
#pragma unroll
            for (int i = 0; i < 4; i++) pv[i] = KP[(r0 + i) * KP_STRIDE + kk];
#pragma unroll
            for (int j = 0; j < 4; j++) vv[j] = Vs[kk * 64 + c0 + j];
#pragma unroll
            for (int i = 0; i < 4; i++)
#pragma unroll
                for (int j = 0; j < 4; j++) o[i][j] = fmaf(pv[i], vv[j], o[i][j]);
        }
        __syncthreads();   // done reading P/V before next tile load
    }

    // Epilogue: normalize and write to g_att[b, l, h*64 + d]
    float* obase = g_att + (size_t)b * L_SEQ * DIM + h * DH;
#pragma unroll
    for (int i = 0; i < 4; i++) {
        float inv = 1.0f / lsum[i];
        int row = qt * 64 + r0 + i;
        float v[4];
#pragma unroll
        for (int j = 0; j < 4; j++) v[j] = o[i][j] * inv;
        *(float4*)(obase + (size_t)row * DIM + c0) = *(float4*)v;
    }
}

// ---------------------------------------------------------------------------
extern "C" void kernel_launch(void* const* d_in, const int* in_sizes, int n_in,
                              void* d_out, int out_size)
{
    const float* x      = (const float*)d_in[0];
    const float* w_qkv  = (const float*)d_in[1];
    const float* w_proj = (const float*)d_in[2];
    const float* b_proj = (const float*)d_in[3];
    float* out = (float*)d_out;

    float *qkv_ptr, *att_ptr;
    cudaGetSymbolAddress((void**)&qkv_ptr, g_qkv);
    cudaGetSymbolAddress((void**)&att_ptr, g_att);

    cudaFuncSetAttribute(flash_kernel,
                         cudaFuncAttributeMaxDynamicSharedMemorySize, FLASH_SMEM);

    const int M = BATCH * L_SEQ;  // 4096

    // 1) QKV projection: [4096,1024] @ [1024,3072]
    sgemm_kernel<<<dim3(QKV_COLS / 128, M / 128), 256>>>(
        x, w_qkv, qkv_ptr, M, QKV_COLS, DIM, nullptr);

    // 2) Attention
    flash_kernel<<<dim3(L_SEQ / 64, HEADS, BATCH), 256, FLASH_SMEM>>>();

    // 3) Output projection + bias: [4096,1024] @ [1024,1024]
    sgemm_kernel<<<dim3(DIM / 128, M / 128), 256>>>(
        att_ptr, w_proj, out, M, DIM, DIM, b_proj);
}

// round 6
// speedup vs baseline: 2.3239x; 2.3239x over previous
#include <cuda_runtime.h>
#include <math.h>
#include <stdint.h>

#define BATCH   2
#define L_SEQ   2048
#define DIM     1024
#define HEADS   16
#define DH      64
#define QKV_COLS 3072
#define PHI_F   1.6180339887498949f

// Scratch (device globals: allocation-free rule)
__device__ float g_qkv[(size_t)BATCH * L_SEQ * QKV_COLS];  // ~50 MB
__device__ float g_att[(size_t)BATCH * L_SEQ * DIM];       // ~17 MB

// ---------------------------------------------------------------------------
// helpers
// ---------------------------------------------------------------------------
__device__ __forceinline__ uint32_t f2tf32(float x) {
    uint32_t r;
    asm("cvt.rna.tf32.f32 %0, %1;" : "=r"(r) : "f"(x));
    return r;
}
__device__ __forceinline__ float4 cvt4(float4 v) {
    v.x = __uint_as_float(f2tf32(v.x));
    v.y = __uint_as_float(f2tf32(v.y));
    v.z = __uint_as_float(f2tf32(v.z));
    v.w = __uint_as_float(f2tf32(v.w));
    return v;
}
__device__ __forceinline__ void mma8(float* c, uint32_t a0, uint32_t a1,
                                     uint32_t a2, uint32_t a3,
                                     uint32_t b0, uint32_t b1) {
    asm("mma.sync.aligned.m16n8k8.row.col.f32.tf32.tf32.f32 "
        "{%0,%1,%2,%3}, {%4,%5,%6,%7}, {%8,%9}, {%0,%1,%2,%3};"
        : "+f"(c[0]), "+f"(c[1]), "+f"(c[2]), "+f"(c[3])
        : "r"(a0), "r"(a1), "r"(a2), "r"(a3), "r"(b0), "r"(b1));
}
// Fast e^x for x <= 0 on the FMA pipe (MUFU rt=8/SMSP makes __expf a bottleneck)
__device__ __forceinline__ float fexp(float x) {
    x = fmaxf(x, -87.0f);
    float t = x * 1.4426950408889634f;   // log2(e)
    float n = rintf(t);
    float f = t - n;
    float p = 1.3333557e-3f;             // 2^f Taylor/minimax, |f|<=0.5
    p = fmaf(p, f, 9.6181291e-3f);
    p = fmaf(p, f, 5.5504109e-2f);
    p = fmaf(p, f, 2.4022651e-1f);
    p = fmaf(p, f, 6.9314718e-1f);
    p = fmaf(p, f, 1.0f);
    int e = (int)n;
    return p * __int_as_float((e + 127) << 23);
}

// ---------------------------------------------------------------------------
// tf32 mma GEMM: C[M,N] = A[M,K] @ B[K,N] (+bias). 128x128x16 tile,
// 256 thr (8 warps, 4x2), warp tile 32x64. Conflict-free frag strides.
// ---------------------------------------------------------------------------
#define AST 20    // As row stride (floats): (20*r + c) % 32 conflict-free frags
#define BST 136   // Bs row stride: (136*k + n) % 32 -> 8*qid + grp conflict-free

__global__ __launch_bounds__(256) void gemm_tf32(
    const float* __restrict__ A, const float* __restrict__ B,
    float* __restrict__ C, int M, int N, int K,
    const float* __restrict__ bias)
{
    __shared__ float As[128 * AST];
    __shared__ float Bs[16 * BST];

    const int tid = threadIdx.x;
    const int lane = tid & 31, wid = tid >> 5;
    const int wm = wid >> 1, wn = wid & 1;
    const int grp = lane >> 2, qid = lane & 3;
    const int row0 = blockIdx.y * 128;
    const int col0 = blockIdx.x * 128;

    float acc[2][8][4];
#pragma unroll
    for (int mf = 0; mf < 2; mf++)
#pragma unroll
        for (int nf = 0; nf < 8; nf++)
#pragma unroll
            for (int i = 0; i < 4; i++) acc[mf][nf][i] = 0.0f;

    // thread's load coords
    const int ar0 = tid >> 2,  ac0 = (tid & 3) << 2;    // +128 rows for it=1
    const int br0 = tid >> 5,  bc0 = (tid & 31) << 2;   // +8 k-rows for it=1

    float4 pa[2], pb[2];
    // prefetch tile 0
#pragma unroll
    for (int it = 0; it < 2; it++) {
        pa[it] = *(const float4*)(A + (size_t)(row0 + ar0 + it * 64) * K + ac0);
        pb[it] = *(const float4*)(B + (size_t)(br0 + it * 8) * N + col0 + bc0);
    }

    for (int k0 = 0; k0 < K; k0 += 16) {
        // store prefetched tile
#pragma unroll
        for (int it = 0; it < 2; it++) {
            *(float4*)&As[(ar0 + it * 64) * AST + ac0] = cvt4(pa[it]);
            *(float4*)&Bs[(br0 + it * 8) * BST + bc0] = cvt4(pb[it]);
        }
        __syncthreads();
        // prefetch next
        if (k0 + 16 < K) {
#pragma unroll
            for (int it = 0; it < 2; it++) {
                pa[it] = *(const float4*)(A + (size_t)(row0 + ar0 + it * 64) * K + k0 + 16 + ac0);
                pb[it] = *(const float4*)(B + (size_t)(k0 + 16 + br0 + it * 8) * N + col0 + bc0);
            }
        }
#pragma unroll
        for (int ks = 0; ks < 2; ks++) {
            const int kb = ks * 8;
            uint32_t a[2][4];
#pragma unroll
            for (int mf = 0; mf < 2; mf++) {
                int r = wm * 32 + mf * 16 + grp;
                a[mf][0] = __float_as_uint(As[r * AST + kb + qid]);
                a[mf][1] = __float_as_uint(As[(r + 8) * AST + kb + qid]);
                a[mf][2] = __float_as_uint(As[r * AST + kb + qid + 4]);
                a[mf][3] = __float_as_uint(As[(r + 8) * AST + kb + qid + 4]);
            }
#pragma unroll
            for (int nf = 0; nf < 8; nf++) {
                int n = wn * 64 + nf * 8 + grp;
                uint32_t b0 = __float_as_uint(Bs[(kb + qid) * BST + n]);
                uint32_t b1 = __float_as_uint(Bs[(kb + qid + 4) * BST + n]);
                mma8(acc[0][nf], a[0][0], a[0][1], a[0][2], a[0][3], b0, b1);
                mma8(acc[1][nf], a[1][0], a[1][1], a[1][2], a[1][3], b0, b1);
            }
        }
        __syncthreads();
    }

#pragma unroll
    for (int mf = 0; mf < 2; mf++) {
#pragma unroll
        for (int nf = 0; nf < 8; nf++) {
            int r = row0 + wm * 32 + mf * 16 + grp;
            int c = col0 + wn * 64 + nf * 8 + 2 * qid;
            float b0v = bias ? bias[c] : 0.0f;
            float b1v = bias ? bias[c + 1] : 0.0f;
            float2 lo = make_float2(acc[mf][nf][0] + b0v, acc[mf][nf][1] + b1v);
            float2 hi = make_float2(acc[mf][nf][2] + b0v, acc[mf][nf][3] + b1v);
            *(float2*)(C + (size_t)r * N + c) = lo;
            *(float2*)(C + (size_t)(r + 8) * N + c) = hi;
        }
    }
}

// ---------------------------------------------------------------------------
// Flash attention on tf32 mma. Grid (32, 16, 2), 128 thr (4 warps).
// Warp owns 16 q rows. BM=64, BN=64, Dh=64.
// Smem: Qs[64][68], Ks[64][68], Ps[64][68] (also V stage), Vt[64][69].
// ---------------------------------------------------------------------------
#define FST 68
#define VST 69
#define FLASH_SMEM ((64 * FST * 3 + 64 * VST) * 4)

__global__ __launch_bounds__(128) void flash_tf32()
{
    extern __shared__ float sm[];
    float* Qs = sm;
    float* Ks = Qs + 64 * FST;
    float* Ps = Ks + 64 * FST;     // V staging buffer, then P
    float* Vt = Ps + 64 * FST;     // [d][j]

    const int qt = blockIdx.x, h = blockIdx.y, b = blockIdx.z;
    const int tid = threadIdx.x, lane = tid & 31, w = tid >> 5;
    const int grp = lane >> 2, qid = lane & 3;

    const float* qbase = g_qkv + (size_t)b * L_SEQ * QKV_COLS + h * DH;
    const float* kbase = qbase + DIM;
    const float* vbase = qbase + 2 * DIM;

    // load Q tile (cvt to tf32)
#pragma unroll
    for (int it = 0; it < 8; it++) {
        int idx = tid + it * 128;
        int r = idx >> 4, c4 = (idx & 15) << 2;
        float4 v = *(const float4*)(qbase + (size_t)(qt * 64 + r) * QKV_COLS + c4);
        *(float4*)&Qs[r * FST + c4] = cvt4(v);
    }

    const int rlo = w * 16 + grp;
    const float pq0 = fmodf((float)(qt * 64 + rlo) * PHI_F, 1.0f);
    const float pq1 = fmodf((float)(qt * 64 + rlo + 8) * PHI_F, 1.0f);

    float m0 = -1e30f, m1 = -1e30f, l0 = 0.0f, l1 = 0.0f;
    float o[8][4];
#pragma unroll
    for (int df = 0; df < 8; df++)
#pragma unroll
        for (int i = 0; i < 4; i++) o[df][i] = 0.0f;

    for (int kt = 0; kt < L_SEQ / 64; kt++) {
        __syncthreads();   // prev iter's Ps/Vt/Ks reads done
        // load K -> Ks, V -> Ps (stage), coalesced, cvt tf32
#pragma unroll
        for (int it = 0; it < 8; it++) {
            int idx = tid + it * 128;
            int r = idx >> 4, c4 = (idx & 15) << 2;
            float4 kv = *(const float4*)(kbase + (size_t)(kt * 64 + r) * QKV_COLS + c4);
            *(float4*)&Ks[r * FST + c4] = cvt4(kv);
            float4 vv = *(const float4*)(vbase + (size_t)(kt * 64 + r) * QKV_COLS + c4);
            *(float4*)&Ps[r * FST + c4] = cvt4(vv);
        }
        __syncthreads();
        // transpose V stage -> Vt[d][j]
#pragma unroll
        for (int it = 0; it < 8; it++) {
            int idx = tid + it * 128;
            int j = idx >> 4, d4 = (idx & 15) << 2;
            float4 v = *(float4*)&Ps[j * FST + d4];
            Vt[(d4 + 0) * VST + j] = v.x;
            Vt[(d4 + 1) * VST + j] = v.y;
            Vt[(d4 + 2) * VST + j] = v.z;
            Vt[(d4 + 3) * VST + j] = v.w;
        }
        __syncthreads();

        // S = Q @ K^T  (warp: 16 x 64)
        float s[8][4];
#pragma unroll
        for (int nf = 0; nf < 8; nf++)
#pragma unroll
            for (int i = 0; i < 4; i++) s[nf][i] = 0.0f;
#pragma unroll
        for (int kb = 0; kb < 64; kb += 8) {
            uint32_t a0 = __float_as_uint(Qs[rlo * FST + kb + qid]);
            uint32_t a1 = __float_as_uint(Qs[(rlo + 8) * FST + kb + qid]);
            uint32_t a2 = __float_as_uint(Qs[rlo * FST + kb + qid + 4]);
            uint32_t a3 = __float_as_uint(Qs[(rlo + 8) * FST + kb + qid + 4]);
#pragma unroll
            for (int nf = 0; nf < 8; nf++) {
                uint32_t b0 = __float_as_uint(Ks[(nf * 8 + grp) * FST + kb + qid]);
                uint32_t b1 = __float_as_uint(Ks[(nf * 8 + grp) * FST + kb + qid + 4]);
                mma8(s[nf], a0, a1, a2, a3, b0, b1);
            }
        }

        // logits = s*scale - |pq - pk|  (phi bias); row max
        float mx0 = -1e30f, mx1 = -1e30f;
#pragma unroll
        for (int nf = 0; nf < 8; nf++) {
#pragma unroll
            for (int c = 0; c < 2; c++) {
                int j = kt * 64 + nf * 8 + 2 * qid + c;
                float pk = fmodf((float)j * PHI_F, 1.0f);
                float v0 = s[nf][c] * 0.125f - fabsf(pq0 - pk);
                float v1 = s[nf][2 + c] * 0.125f - fabsf(pq1 - pk);
                s[nf][c] = v0; s[nf][2 + c] = v1;
                mx0 = fmaxf(mx0, v0); mx1 = fmaxf(mx1, v1);
            }
        }
        mx0 = fmaxf(mx0, __shfl_xor_sync(0xffffffffu, mx0, 1));
        mx0 = fmaxf(mx0, __shfl_xor_sync(0xffffffffu, mx0, 2));
        mx1 = fmaxf(mx1, __shfl_xor_sync(0xffffffffu, mx1, 1));
        mx1 = fmaxf(mx1, __shfl_xor_sync(0xffffffffu, mx1, 2));

        float mn0 = fmaxf(m0, mx0), mn1 = fmaxf(m1, mx1);
        float c0 = fexp(m0 - mn0), c1 = fexp(m1 - mn1);
        float rs0 = 0.0f, rs1 = 0.0f;
#pragma unroll
        for (int nf = 0; nf < 8; nf++) {
            float p00 = fexp(s[nf][0] - mn0);
            float p01 = fexp(s[nf][1] - mn0);
            float p10 = fexp(s[nf][2] - mn1);
            float p11 = fexp(s[nf][3] - mn1);
            rs0 += p00 + p01; rs1 += p10 + p11;
            int cl = nf * 8 + 2 * qid;
            *(float2*)&Ps[rlo * FST + cl] =
                make_float2(__uint_as_float(f2tf32(p00)), __uint_as_float(f2tf32(p01)));
            *(float2*)&Ps[(rlo + 8) * FST + cl] =
                make_float2(__uint_as_float(f2tf32(p10)), __uint_as_float(f2tf32(p11)));
        }
        rs0 += __shfl_xor_sync(0xffffffffu, rs0, 1);
        rs0 += __shfl_xor_sync(0xffffffffu, rs0, 2);
        rs1 += __shfl_xor_sync(0xffffffffu, rs1, 1);
        rs1 += __shfl_xor_sync(0xffffffffu, rs1, 2);
        l0 = l0 * c0 + rs0; l1 = l1 * c1 + rs1;
        m0 = mn0; m1 = mn1;
#pragma unroll
        for (int df = 0; df < 8; df++) {
            o[df][0] *= c0; o[df][1] *= c0;
            o[df][2] *= c1; o[df][3] *= c1;
        }
        __syncwarp();   // P rows are warp-private: warp-level sync suffices

        // O += P @ V   (A = P[16 x 64], B = Vt)
#pragma unroll
        for (int kb = 0; kb < 64; kb += 8) {
            uint32_t a0 = __float_as_uint(Ps[rlo * FST + kb + qid]);
            uint32_t a1 = __float_as_uint(Ps[(rlo + 8) * FST + kb + qid]);
            uint32_t a2 = __float_as_uint(Ps[rlo * FST + kb + qid + 4]);
            uint32_t a3 = __float_as_uint(Ps[(rlo + 8) * FST + kb + qid + 4]);
#pragma unroll
            for (int df = 0; df < 8; df++) {
                uint32_t b0 = __float_as_uint(Vt[(df * 8 + grp) * VST + kb + qid]);
                uint32_t b1 = __float_as_uint(Vt[(df * 8 + grp) * VST + kb + qid + 4]);
                mma8(o[df], a0, a1, a2, a3, b0, b1);
            }
        }
    }

    // epilogue
    float inv0 = 1.0f / l0, inv1 = 1.0f / l1;
    float* obase = g_att + (size_t)b * L_SEQ * DIM + h * DH;
    int row = qt * 64 + rlo;
#pragma unroll
    for (int df = 0; df < 8; df++) {
        int cl = df * 8 + 2 * qid;
        *(float2*)(obase + (size_t)row * DIM + cl) =
            make_float2(o[df][0] * inv0, o[df][1] * inv0);
        *(float2*)(obase + (size_t)(row + 8) * DIM + cl) =
            make_float2(o[df][2] * inv1, o[df][3] * inv1);
    }
}

// ---------------------------------------------------------------------------
extern "C" void kernel_launch(void* const* d_in, const int* in_sizes, int n_in,
                              void* d_out, int out_size)
{
    const float* x      = (const float*)d_in[0];
    const float* w_qkv  = (const float*)d_in[1];
    const float* w_proj = (const float*)d_in[2];
    const float* b_proj = (const float*)d_in[3];
    float* out = (float*)d_out;

    float *qkv_ptr, *att_ptr;
    cudaGetSymbolAddress((void**)&qkv_ptr, g_qkv);
    cudaGetSymbolAddress((void**)&att_ptr, g_att);

    cudaFuncSetAttribute(flash_tf32,
                         cudaFuncAttributeMaxDynamicSharedMemorySize, FLASH_SMEM);

    const int M = BATCH * L_SEQ;  // 4096

    gemm_tf32<<<dim3(QKV_COLS / 128, M / 128), 256>>>(
        x, w_qkv, qkv_ptr, M, QKV_COLS, DIM, nullptr);

    flash_tf32<<<dim3(L_SEQ / 64, HEADS, BATCH), 128, FLASH_SMEM>>>();

    gemm_tf32<<<dim3(DIM / 128, M / 128), 256>>>(
        att_ptr, w_proj, out, M, DIM, DIM, b_proj);
}

// round 9
// speedup vs baseline: 2.6170x; 1.1261x over previous
#include <cuda_runtime.h>
#include <math.h>
#include <stdint.h>

#define BATCH   2
#define L_SEQ   2048
#define DIM     1024
#define HEADS   16
#define DH      64
#define QKV_COLS 3072
#define PHI_F   1.6180339887498949f

// Scratch (device globals: allocation-free rule)
__device__ float g_qkv[(size_t)BATCH * L_SEQ * QKV_COLS];  // ~50 MB
__device__ float g_att[(size_t)BATCH * L_SEQ * DIM];       // ~17 MB

// ---------------------------------------------------------------------------
// helpers
// ---------------------------------------------------------------------------
__device__ __forceinline__ uint32_t f2tf32(float x) {
    uint32_t r;
    asm("cvt.rna.tf32.f32 %0, %1;" : "=r"(r) : "f"(x));
    return r;
}
__device__ __forceinline__ float4 cvt4(float4 v) {
    v.x = __uint_as_float(f2tf32(v.x));
    v.y = __uint_as_float(f2tf32(v.y));
    v.z = __uint_as_float(f2tf32(v.z));
    v.w = __uint_as_float(f2tf32(v.w));
    return v;
}
__device__ __forceinline__ void mma8(float* c, uint32_t a0, uint32_t a1,
                                     uint32_t a2, uint32_t a3,
                                     uint32_t b0, uint32_t b1) {
    asm("mma.sync.aligned.m16n8k8.row.col.f32.tf32.tf32.f32 "
        "{%0,%1,%2,%3}, {%4,%5,%6,%7}, {%8,%9}, {%0,%1,%2,%3};"
        : "+f"(c[0]), "+f"(c[1]), "+f"(c[2]), "+f"(c[3])
        : "r"(a0), "r"(a1), "r"(a2), "r"(a3), "r"(b0), "r"(b1));
}
// Fast e^x for x <= 0 on the FMA pipe (MUFU rt=8/SMSP makes __expf a bottleneck)
__device__ __forceinline__ float fexp(float x) {
    x = fmaxf(x, -87.0f);
    float t = x * 1.4426950408889634f;   // log2(e)
    float n = rintf(t);
    float f = t - n;
    float p = 1.3333557e-3f;             // 2^f Taylor/minimax, |f|<=0.5
    p = fmaf(p, f, 9.6181291e-3f);
    p = fmaf(p, f, 5.5504109e-2f);
    p = fmaf(p, f, 2.4022651e-1f);
    p = fmaf(p, f, 6.9314718e-1f);
    p = fmaf(p, f, 1.0f);
    int e = (int)n;
    return p * __int_as_float((e + 127) << 23);
}

// ---------------------------------------------------------------------------
// tf32 mma GEMM: C[M,N] = A[M,K] @ B[K,N] (+bias). 128x128x16 tile,
// 256 thr (8 warps, 4x2), warp tile 32x64. Conflict-free frag strides.
// ---------------------------------------------------------------------------
#define AST 20    // As row stride (floats): (20*r + c) % 32 conflict-free frags
#define BST 136   // Bs row stride: (136*k + n) % 32 -> 8*qid + grp conflict-free

__global__ __launch_bounds__(256) void gemm_tf32(
    const float* __restrict__ A, const float* __restrict__ B,
    float* __restrict__ C, int M, int N, int K,
    const float* __restrict__ bias)
{
    __shared__ float As[128 * AST];
    __shared__ float Bs[16 * BST];

    const int tid = threadIdx.x;
    const int lane = tid & 31, wid = tid >> 5;
    const int wm = wid >> 1, wn = wid & 1;
    const int grp = lane >> 2, qid = lane & 3;
    const int row0 = blockIdx.y * 128;
    const int col0 = blockIdx.x * 128;

    float acc[2][8][4];
#pragma unroll
    for (int mf = 0; mf < 2; mf++)
#pragma unroll
        for (int nf = 0; nf < 8; nf++)
#pragma unroll
            for (int i = 0; i < 4; i++) acc[mf][nf][i] = 0.0f;

    // thread's load coords
    const int ar0 = tid >> 2,  ac0 = (tid & 3) << 2;    // +64 rows for it=1
    const int br0 = tid >> 5,  bc0 = (tid & 31) << 2;   // +8 k-rows for it=1

    float4 pa[2], pb[2];
    // prefetch tile 0
#pragma unroll
    for (int it = 0; it < 2; it++) {
        pa[it] = *(const float4*)(A + (size_t)(row0 + ar0 + it * 64) * K + ac0);
        pb[it] = *(const float4*)(B + (size_t)(br0 + it * 8) * N + col0 + bc0);
    }

    for (int k0 = 0; k0 < K; k0 += 16) {
        // store prefetched tile
#pragma unroll
        for (int it = 0; it < 2; it++) {
            *(float4*)&As[(ar0 + it * 64) * AST + ac0] = cvt4(pa[it]);
            *(float4*)&Bs[(br0 + it * 8) * BST + bc0] = cvt4(pb[it]);
        }
        __syncthreads();
        // prefetch next
        if (k0 + 16 < K) {
#pragma unroll
            for (int it = 0; it < 2; it++) {
                pa[it] = *(const float4*)(A + (size_t)(row0 + ar0 + it * 64) * K + k0 + 16 + ac0);
                pb[it] = *(const float4*)(B + (size_t)(k0 + 16 + br0 + it * 8) * N + col0 + bc0);
            }
        }
#pragma unroll
        for (int ks = 0; ks < 2; ks++) {
            const int kb = ks * 8;
            uint32_t a[2][4];
#pragma unroll
            for (int mf = 0; mf < 2; mf++) {
                int r = wm * 32 + mf * 16 + grp;
                a[mf][0] = __float_as_uint(As[r * AST + kb + qid]);
                a[mf][1] = __float_as_uint(As[(r + 8) * AST + kb + qid]);
                a[mf][2] = __float_as_uint(As[r * AST + kb + qid + 4]);
                a[mf][3] = __float_as_uint(As[(r + 8) * AST + kb + qid + 4]);
            }
#pragma unroll
            for (int nf = 0; nf < 8; nf++) {
                int n = wn * 64 + nf * 8 + grp;
                uint32_t b0 = __float_as_uint(Bs[(kb + qid) * BST + n]);
                uint32_t b1 = __float_as_uint(Bs[(kb + qid + 4) * BST + n]);
                mma8(acc[0][nf], a[0][0], a[0][1], a[0][2], a[0][3], b0, b1);
                mma8(acc[1][nf], a[1][0], a[1][1], a[1][2], a[1][3], b0, b1);
            }
        }
        __syncthreads();
    }

#pragma unroll
    for (int mf = 0; mf < 2; mf++) {
#pragma unroll
        for (int nf = 0; nf < 8; nf++) {
            int r = row0 + wm * 32 + mf * 16 + grp;
            int c = col0 + wn * 64 + nf * 8 + 2 * qid;
            float b0v = bias ? bias[c] : 0.0f;
            float b1v = bias ? bias[c + 1] : 0.0f;
            float2 lo = make_float2(acc[mf][nf][0] + b0v, acc[mf][nf][1] + b1v);
            float2 hi = make_float2(acc[mf][nf][2] + b0v, acc[mf][nf][3] + b1v);
            *(float2*)(C + (size_t)r * N + c) = lo;
            *(float2*)(C + (size_t)(r + 8) * N + c) = hi;
        }
    }
}

// ---------------------------------------------------------------------------
// Flash attention on tf32 mma. BM=128, BN=64, Dh=64.
// Grid (L/128, HEADS, BATCH), 256 thr (8 warps); warp owns 16 q rows.
// Smem: Qs[128][68], Ks[64][68], Ps[128][68], Vs[64][72] (natural [j][d]
// layout serves directly as the col-major B operand of P@V -- no transpose).
// ---------------------------------------------------------------------------
#define FST 68
#define VST 72
#define FLASH_SMEM ((128 * FST + 64 * FST + 128 * FST + 64 * VST) * 4)

__global__ __launch_bounds__(256, 2) void flash_tf32()
{
    extern __shared__ float sm[];
    float* Qs = sm;                    // [128][68]
    float* Ks = Qs + 128 * FST;        // [64][68]
    float* Ps = Ks + 64 * FST;         // [128][68]
    float* Vs = Ps + 128 * FST;        // [64][72]  natural V[j][d]

    const int qt = blockIdx.x, h = blockIdx.y, b = blockIdx.z;
    const int tid = threadIdx.x, lane = tid & 31, w = tid >> 5;
    const int grp = lane >> 2, qid = lane & 3;

    const float* qbase = g_qkv + (size_t)b * L_SEQ * QKV_COLS + h * DH;
    const float* kbase = qbase + DIM;
    const float* vbase = qbase + 2 * DIM;

    // load Q tile: 128 rows (cvt to tf32)
#pragma unroll
    for (int it = 0; it < 8; it++) {
        int idx = tid + it * 256;
        int r = idx >> 4, c4 = (idx & 15) << 2;
        float4 v = *(const float4*)(qbase + (size_t)(qt * 128 + r) * QKV_COLS + c4);
        *(float4*)&Qs[r * FST + c4] = cvt4(v);
    }

    const int rlo = w * 16 + grp;      // warp-private q rows: rlo, rlo+8
    const float pq0 = fmodf((float)(qt * 128 + rlo) * PHI_F, 1.0f);
    const float pq1 = fmodf((float)(qt * 128 + rlo + 8) * PHI_F, 1.0f);

    float m0 = -1e30f, m1 = -1e30f, l0 = 0.0f, l1 = 0.0f;
    float o[8][4];
#pragma unroll
    for (int df = 0; df < 8; df++)
#pragma unroll
        for (int i = 0; i < 4; i++) o[df][i] = 0.0f;

    for (int kt = 0; kt < L_SEQ / 64; kt++) {
        __syncthreads();   // prev iter's Ks/Vs reads done (also guards Qs at kt=0)
        // load K -> Ks, V -> Vs (coalesced, cvt tf32)
#pragma unroll
        for (int it = 0; it < 4; it++) {
            int idx = tid + it * 256;
            int r = idx >> 4, c4 = (idx & 15) << 2;
            float4 kv = *(const float4*)(kbase + (size_t)(kt * 64 + r) * QKV_COLS + c4);
            *(float4*)&Ks[r * FST + c4] = cvt4(kv);
            float4 vv = *(const float4*)(vbase + (size_t)(kt * 64 + r) * QKV_COLS + c4);
            *(float4*)&Vs[r * VST + c4] = cvt4(vv);
        }
        __syncthreads();

        // S = Q @ K^T  (warp: 16 x 64)
        float s[8][4];
#pragma unroll
        for (int nf = 0; nf < 8; nf++)
#pragma unroll
            for (int i = 0; i < 4; i++) s[nf][i] = 0.0f;
#pragma unroll
        for (int kb = 0; kb < 64; kb += 8) {
            uint32_t a0 = __float_as_uint(Qs[rlo * FST + kb + qid]);
            uint32_t a1 = __float_as_uint(Qs[(rlo + 8) * FST + kb + qid]);
            uint32_t a2 = __float_as_uint(Qs[rlo * FST + kb + qid + 4]);
            uint32_t a3 = __float_as_uint(Qs[(rlo + 8) * FST + kb + qid + 4]);
#pragma unroll
            for (int nf = 0; nf < 8; nf++) {
                uint32_t b0 = __float_as_uint(Ks[(nf * 8 + grp) * FST + kb + qid]);
                uint32_t b1 = __float_as_uint(Ks[(nf * 8 + grp) * FST + kb + qid + 4]);
                mma8(s[nf], a0, a1, a2, a3, b0, b1);
            }
        }

        // logits = s*scale - |pq - pk|  (phi bias); row max
        float mx0 = -1e30f, mx1 = -1e30f;
#pragma unroll
        for (int nf = 0; nf < 8; nf++) {
#pragma unroll
            for (int c = 0; c < 2; c++) {
                int j = kt * 64 + nf * 8 + 2 * qid + c;
                float pk = fmodf((float)j * PHI_F, 1.0f);
                float v0 = s[nf][c] * 0.125f - fabsf(pq0 - pk);
                float v1 = s[nf][2 + c] * 0.125f - fabsf(pq1 - pk);
                s[nf][c] = v0; s[nf][2 + c] = v1;
                mx0 = fmaxf(mx0, v0); mx1 = fmaxf(mx1, v1);
            }
        }
        mx0 = fmaxf(mx0, __shfl_xor_sync(0xffffffffu, mx0, 1));
        mx0 = fmaxf(mx0, __shfl_xor_sync(0xffffffffu, mx0, 2));
        mx1 = fmaxf(mx1, __shfl_xor_sync(0xffffffffu, mx1, 1));
        mx1 = fmaxf(mx1, __shfl_xor_sync(0xffffffffu, mx1, 2));

        float mn0 = fmaxf(m0, mx0), mn1 = fmaxf(m1, mx1);
        float c0 = fexp(m0 - mn0), c1 = fexp(m1 - mn1);
        float rs0 = 0.0f, rs1 = 0.0f;
#pragma unroll
        for (int nf = 0; nf < 8; nf++) {
            float p00 = fexp(s[nf][0] - mn0);
            float p01 = fexp(s[nf][1] - mn0);
            float p10 = fexp(s[nf][2] - mn1);
            float p11 = fexp(s[nf][3] - mn1);
            rs0 += p00 + p01; rs1 += p10 + p11;
            int cl = nf * 8 + 2 * qid;
            *(float2*)&Ps[rlo * FST + cl] =
                make_float2(__uint_as_float(f2tf32(p00)), __uint_as_float(f2tf32(p01)));
            *(float2*)&Ps[(rlo + 8) * FST + cl] =
                make_float2(__uint_as_float(f2tf32(p10)), __uint_as_float(f2tf32(p11)));
        }
        rs0 += __shfl_xor_sync(0xffffffffu, rs0, 1);
        rs0 += __shfl_xor_sync(0xffffffffu, rs0, 2);
        rs1 += __shfl_xor_sync(0xffffffffu, rs1, 1);
        rs1 += __shfl_xor_sync(0xffffffffu, rs1, 2);
        l0 = l0 * c0 + rs0; l1 = l1 * c1 + rs1;
        m0 = mn0; m1 = mn1;
#pragma unroll
        for (int df = 0; df < 8; df++) {
            o[df][0] *= c0; o[df][1] *= c0;
            o[df][2] *= c1; o[df][3] *= c1;
        }
        __syncwarp();   // P rows are warp-private: warp-level sync suffices

        // O += P @ V   (A = P[16 x 64] warp rows, B = Vs[j][d] natural layout)
#pragma unroll
        for (int kb = 0; kb < 64; kb += 8) {
            uint32_t a0 = __float_as_uint(Ps[rlo * FST + kb + qid]);
            uint32_t a1 = __float_as_uint(Ps[(rlo + 8) * FST + kb + qid]);
            uint32_t a2 = __float_as_uint(Ps[rlo * FST + kb + qid + 4]);
            uint32_t a3 = __float_as_uint(Ps[(rlo + 8) * FST + kb + qid + 4]);
#pragma unroll
            for (int df = 0; df < 8; df++) {
                uint32_t b0 = __float_as_uint(Vs[(kb + qid) * VST + df * 8 + grp]);
                uint32_t b1 = __float_as_uint(Vs[(kb + qid + 4) * VST + df * 8 + grp]);
                mma8(o[df], a0, a1, a2, a3, b0, b1);
            }
        }
    }

    // epilogue
    float inv0 = 1.0f / l0, inv1 = 1.0f / l1;
    float* obase = g_att + (size_t)b * L_SEQ * DIM + h * DH;
    int row = qt * 128 + rlo;
#pragma unroll
    for (int df = 0; df < 8; df++) {
        int cl = df * 8 + 2 * qid;
        *(float2*)(obase + (size_t)row * DIM + cl) =
            make_float2(o[df][0] * inv0, o[df][1] * inv0);
        *(float2*)(obase + (size_t)(row + 8) * DIM + cl) =
            make_float2(o[df][2] * inv1, o[df][3] * inv1);
    }
}

// ---------------------------------------------------------------------------
extern "C" void kernel_launch(void* const* d_in, const int* in_sizes, int n_in,
                              void* d_out, int out_size)
{
    const float* x      = (const float*)d_in[0];
    const float* w_qkv  = (const float*)d_in[1];
    const float* w_proj = (const float*)d_in[2];
    const float* b_proj = (const float*)d_in[3];
    float* out = (float*)d_out;

    float *qkv_ptr, *att_ptr;
    cudaGetSymbolAddress((void**)&qkv_ptr, g_qkv);
    cudaGetSymbolAddress((void**)&att_ptr, g_att);

    cudaFuncSetAttribute(flash_tf32,
                         cudaFuncAttributeMaxDynamicSharedMemorySize, FLASH_SMEM);

    const int M = BATCH * L_SEQ;  // 4096

    gemm_tf32<<<dim3(QKV_COLS / 128, M / 128), 256>>>(
        x, w_qkv, qkv_ptr, M, QKV_COLS, DIM, nullptr);

    flash_tf32<<<dim3(L_SEQ / 128, HEADS, BATCH), 256, FLASH_SMEM>>>();

    gemm_tf32<<<dim3(DIM / 128, M / 128), 256>>>(
        att_ptr, w_proj, out, M, DIM, DIM, b_proj);
}

// round 13
// speedup vs baseline: 2.7382x; 1.0463x over previous
#include <cuda_runtime.h>
#include <math.h>
#include <stdint.h>

#define BATCH   2
#define L_SEQ   2048
#define DIM     1024
#define HEADS   16
#define DH      64
#define QKV_COLS 3072
#define PHI_F   1.6180339887498949f
#define L2E     1.4426950408889634f

// Scratch (device globals: allocation-free rule)
__device__ float g_qkv[(size_t)BATCH * L_SEQ * QKV_COLS];  // ~50 MB
__device__ float g_att[(size_t)BATCH * L_SEQ * DIM];       // ~17 MB
__device__ float g_pos[L_SEQ];                             // phi positions * log2e

// ---------------------------------------------------------------------------
// helpers
// ---------------------------------------------------------------------------
__device__ __forceinline__ uint32_t f2tf32(float x) {
    uint32_t r;
    asm("cvt.rna.tf32.f32 %0, %1;" : "=r"(r) : "f"(x));
    return r;
}
__device__ __forceinline__ float4 cvt4(float4 v) {
    v.x = __uint_as_float(f2tf32(v.x));
    v.y = __uint_as_float(f2tf32(v.y));
    v.z = __uint_as_float(f2tf32(v.z));
    v.w = __uint_as_float(f2tf32(v.w));
    return v;
}
__device__ __forceinline__ float4 cvt4s(float4 v, float s) {
    v.x = __uint_as_float(f2tf32(v.x * s));
    v.y = __uint_as_float(f2tf32(v.y * s));
    v.z = __uint_as_float(f2tf32(v.z * s));
    v.w = __uint_as_float(f2tf32(v.w * s));
    return v;
}
__device__ __forceinline__ void mma8(float* c, uint32_t a0, uint32_t a1,
                                     uint32_t a2, uint32_t a3,
                                     uint32_t b0, uint32_t b1) {
    asm("mma.sync.aligned.m16n8k8.row.col.f32.tf32.tf32.f32 "
        "{%0,%1,%2,%3}, {%4,%5,%6,%7}, {%8,%9}, {%0,%1,%2,%3};"
        : "+f"(c[0]), "+f"(c[1]), "+f"(c[2]), "+f"(c[3])
        : "r"(a0), "r"(a1), "r"(a2), "r"(a3), "r"(b0), "r"(b1));
}
// 2^x for x <= 0 on the FMA pipe (inputs already in log2 domain)
__device__ __forceinline__ float fexp2(float x) {
    x = fmaxf(x, -126.0f);
    float n = rintf(x);
    float f = x - n;
    float p = 1.3333557e-3f;             // 2^f minimax, |f|<=0.5
    p = fmaf(p, f, 9.6181291e-3f);
    p = fmaf(p, f, 5.5504109e-2f);
    p = fmaf(p, f, 2.4022651e-1f);
    p = fmaf(p, f, 6.9314718e-1f);
    p = fmaf(p, f, 1.0f);
    int e = (int)n;
    return p * __int_as_float((e + 127) << 23);
}

// ---------------------------------------------------------------------------
// phi position table: g_pos[i] = fmodf(i*phi, 1) * log2(e)
// ---------------------------------------------------------------------------
__global__ void pos_init()
{
    int i = blockIdx.x * 256 + threadIdx.x;
    if (i < L_SEQ)
        g_pos[i] = fmodf((float)i * PHI_F, 1.0f) * L2E;
}

// ---------------------------------------------------------------------------
// tf32 mma GEMM: C[M,N] = A[M,K] @ B[K,N] (+bias). 128x128x16 tile,
// 256 thr (8 warps, 4x2), warp tile 32x64. Conflict-free frag strides.
// (verified R9 kernel, unchanged)
// ---------------------------------------------------------------------------
#define AST 20
#define BST 136

__global__ __launch_bounds__(256) void gemm_tf32(
    const float* __restrict__ A, const float* __restrict__ B,
    float* __restrict__ C, int M, int N, int K,
    const float* __restrict__ bias)
{
    __shared__ float As[128 * AST];
    __shared__ float Bs[16 * BST];

    const int tid = threadIdx.x;
    const int lane = tid & 31, wid = tid >> 5;
    const int wm = wid >> 1, wn = wid & 1;
    const int grp = lane >> 2, qid = lane & 3;
    const int row0 = blockIdx.y * 128;
    const int col0 = blockIdx.x * 128;

    float acc[2][8][4];
#pragma unroll
    for (int mf = 0; mf < 2; mf++)
#pragma unroll
        for (int nf = 0; nf < 8; nf++)
#pragma unroll
            for (int i = 0; i < 4; i++) acc[mf][nf][i] = 0.0f;

    const int ar0 = tid >> 2,  ac0 = (tid & 3) << 2;
    const int br0 = tid >> 5,  bc0 = (tid & 31) << 2;

    float4 pa[2], pb[2];
#pragma unroll
    for (int it = 0; it < 2; it++) {
        pa[it] = *(const float4*)(A + (size_t)(row0 + ar0 + it * 64) * K + ac0);
        pb[it] = *(const float4*)(B + (size_t)(br0 + it * 8) * N + col0 + bc0);
    }

    for (int k0 = 0; k0 < K; k0 += 16) {
#pragma unroll
        for (int it = 0; it < 2; it++) {
            *(float4*)&As[(ar0 + it * 64) * AST + ac0] = cvt4(pa[it]);
            *(float4*)&Bs[(br0 + it * 8) * BST + bc0] = cvt4(pb[it]);
        }
        __syncthreads();
        if (k0 + 16 < K) {
#pragma unroll
            for (int it = 0; it < 2; it++) {
                pa[it] = *(const float4*)(A + (size_t)(row0 + ar0 + it * 64) * K + k0 + 16 + ac0);
                pb[it] = *(const float4*)(B + (size_t)(k0 + 16 + br0 + it * 8) * N + col0 + bc0);
            }
        }
#pragma unroll
        for (int ks = 0; ks < 2; ks++) {
            const int kb = ks * 8;
            uint32_t a[2][4];
#pragma unroll
            for (int mf = 0; mf < 2; mf++) {
                int r = wm * 32 + mf * 16 + grp;
                a[mf][0] = __float_as_uint(As[r * AST + kb + qid]);
                a[mf][1] = __float_as_uint(As[(r + 8) * AST + kb + qid]);
                a[mf][2] = __float_as_uint(As[r * AST + kb + qid + 4]);
                a[mf][3] = __float_as_uint(As[(r + 8) * AST + kb + qid + 4]);
            }
#pragma unroll
            for (int nf = 0; nf < 8; nf++) {
                int n = wn * 64 + nf * 8 + grp;
                uint32_t b0 = __float_as_uint(Bs[(kb + qid) * BST + n]);
                uint32_t b1 = __float_as_uint(Bs[(kb + qid + 4) * BST + n]);
                mma8(acc[0][nf], a[0][0], a[0][1], a[0][2], a[0][3], b0, b1);
                mma8(acc[1][nf], a[1][0], a[1][1], a[1][2], a[1][3], b0, b1);
            }
        }
        __syncthreads();
    }

#pragma unroll
    for (int mf = 0; mf < 2; mf++) {
#pragma unroll
        for (int nf = 0; nf < 8; nf++) {
            int r = row0 + wm * 32 + mf * 16 + grp;
            int c = col0 + wn * 64 + nf * 8 + 2 * qid;
            float b0v = bias ? bias[c] : 0.0f;
            float b1v = bias ? bias[c + 1] : 0.0f;
            float2 lo = make_float2(acc[mf][nf][0] + b0v, acc[mf][nf][1] + b1v);
            float2 hi = make_float2(acc[mf][nf][2] + b0v, acc[mf][nf][3] + b1v);
            *(float2*)(C + (size_t)r * N + c) = lo;
            *(float2*)(C + (size_t)(r + 8) * N + c) = hi;
        }
    }
}

// ---------------------------------------------------------------------------
// Flash attention on tf32 mma. BM=128, BN=64, Dh=64.
// Grid (L/128, HEADS, BATCH), 256 thr (8 warps); warp owns 16 q rows.
// Round-13: software-pipelined K/V (reg prefetch), log2-domain softmax
// (0.125*log2e folded into Q; positions pre-scaled in g_pos).
// ---------------------------------------------------------------------------
#define FST 68
#define VST 72
#define FLASH_SMEM ((128 * FST + 64 * FST + 128 * FST + 64 * VST) * 4)

__global__ __launch_bounds__(256, 2) void flash_tf32()
{
    extern __shared__ float sm[];
    float* Qs = sm;                    // [128][68]
    float* Ks = Qs + 128 * FST;        // [64][68]
    float* Ps = Ks + 64 * FST;         // [128][68]
    float* Vs = Ps + 128 * FST;        // [64][72]  natural V[j][d]

    const int qt = blockIdx.x, h = blockIdx.y, b = blockIdx.z;
    const int tid = threadIdx.x, lane = tid & 31, w = tid >> 5;
    const int grp = lane >> 2, qid = lane & 3;

    const float* qbase = g_qkv + (size_t)b * L_SEQ * QKV_COLS + h * DH;
    const float* kbase = qbase + DIM;
    const float* vbase = qbase + 2 * DIM;

    const float QSCL = 0.125f * L2E;   // folded softmax scale (pre-rounding, exact semantics)

    // load Q tile: 128 rows, scaled, cvt tf32
#pragma unroll
    for (int it = 0; it < 8; it++) {
        int idx = tid + it * 256;
        int r = idx >> 4, c4 = (idx & 15) << 2;
        float4 v = *(const float4*)(qbase + (size_t)(qt * 128 + r) * QKV_COLS + c4);
        *(float4*)&Qs[r * FST + c4] = cvt4s(v, QSCL);
    }

    const int rlo = w * 16 + grp;
    const float pq0 = g_pos[qt * 128 + rlo];
    const float pq1 = g_pos[qt * 128 + rlo + 8];

    float m0 = -1e30f, m1 = -1e30f, l0 = 0.0f, l1 = 0.0f;
    float o[8][4];
#pragma unroll
    for (int df = 0; df < 8; df++)
#pragma unroll
        for (int i = 0; i < 4; i++) o[df][i] = 0.0f;

    // per-thread K/V load coords (4 float4 each over the 64x64 tile)
    float4 kreg[4], vreg[4];
#pragma unroll
    for (int it = 0; it < 4; it++) {
        int idx = tid + it * 256;
        int r = idx >> 4, c4 = (idx & 15) << 2;
        kreg[it] = *(const float4*)(kbase + (size_t)r * QKV_COLS + c4);
    }

    for (int kt = 0; kt < L_SEQ / 64; kt++) {
        __syncthreads();   // prior S-phase Ks reads + PV-phase Vs reads done (Qs at kt=0)
        // store prefetched K; issue V loads for this tile
#pragma unroll
        for (int it = 0; it < 4; it++) {
            int idx = tid + it * 256;
            int r = idx >> 4, c4 = (idx & 15) << 2;
            *(float4*)&Ks[r * FST + c4] = cvt4(kreg[it]);
            vreg[it] = *(const float4*)(vbase + (size_t)(kt * 64 + r) * QKV_COLS + c4);
        }
        __syncthreads();   // Ks visible

        // S = Q @ K^T  (warp: 16 x 64) -- result already in log2 units
        float s[8][4];
#pragma unroll
        for (int nf = 0; nf < 8; nf++)
#pragma unroll
            for (int i = 0; i < 4; i++) s[nf][i] = 0.0f;
#pragma unroll
        for (int kb = 0; kb < 64; kb += 8) {
            uint32_t a0 = __float_as_uint(Qs[rlo * FST + kb + qid]);
            uint32_t a1 = __float_as_uint(Qs[(rlo + 8) * FST + kb + qid]);
            uint32_t a2 = __float_as_uint(Qs[rlo * FST + kb + qid + 4]);
            uint32_t a3 = __float_as_uint(Qs[(rlo + 8) * FST + kb + qid + 4]);
#pragma unroll
            for (int nf = 0; nf < 8; nf++) {
                uint32_t b0 = __float_as_uint(Ks[(nf * 8 + grp) * FST + kb + qid]);
                uint32_t b1 = __float_as_uint(Ks[(nf * 8 + grp) * FST + kb + qid + 4]);
                mma8(s[nf], a0, a1, a2, a3, b0, b1);
            }
        }

        // logits (log2 domain): s - |pq - pk|, row max
        float mx0 = -1e30f, mx1 = -1e30f;
#pragma unroll
        for (int nf = 0; nf < 8; nf++) {
#pragma unroll
            for (int c = 0; c < 2; c++) {
                float pk = g_pos[kt * 64 + nf * 8 + 2 * qid + c];
                float v0 = s[nf][c] - fabsf(pq0 - pk);
                float v1 = s[nf][2 + c] - fabsf(pq1 - pk);
                s[nf][c] = v0; s[nf][2 + c] = v1;
                mx0 = fmaxf(mx0, v0); mx1 = fmaxf(mx1, v1);
            }
        }
        mx0 = fmaxf(mx0, __shfl_xor_sync(0xffffffffu, mx0, 1));
        mx0 = fmaxf(mx0, __shfl_xor_sync(0xffffffffu, mx0, 2));
        mx1 = fmaxf(mx1, __shfl_xor_sync(0xffffffffu, mx1, 1));
        mx1 = fmaxf(mx1, __shfl_xor_sync(0xffffffffu, mx1, 2));

        float mn0 = fmaxf(m0, mx0), mn1 = fmaxf(m1, mx1);
        float c0 = fexp2(m0 - mn0), c1 = fexp2(m1 - mn1);
        float rs0 = 0.0f, rs1 = 0.0f;
#pragma unroll
        for (int nf = 0; nf < 8; nf++) {
            float p00 = fexp2(s[nf][0] - mn0);
            float p01 = fexp2(s[nf][1] - mn0);
            float p10 = fexp2(s[nf][2] - mn1);
            float p11 = fexp2(s[nf][3] - mn1);
            rs0 += p00 + p01; rs1 += p10 + p11;
            int cl = nf * 8 + 2 * qid;
            *(float2*)&Ps[rlo * FST + cl] =
                make_float2(__uint_as_float(f2tf32(p00)), __uint_as_float(f2tf32(p01)));
            *(float2*)&Ps[(rlo + 8) * FST + cl] =
                make_float2(__uint_as_float(f2tf32(p10)), __uint_as_float(f2tf32(p11)));
        }
        rs0 += __shfl_xor_sync(0xffffffffu, rs0, 1);
        rs0 += __shfl_xor_sync(0xffffffffu, rs0, 2);
        rs1 += __shfl_xor_sync(0xffffffffu, rs1, 1);
        rs1 += __shfl_xor_sync(0xffffffffu, rs1, 2);
        l0 = l0 * c0 + rs0; l1 = l1 * c1 + rs1;
        m0 = mn0; m1 = mn1;
#pragma unroll
        for (int df = 0; df < 8; df++) {
            o[df][0] *= c0; o[df][1] *= c0;
            o[df][2] *= c1; o[df][3] *= c1;
        }

        // store V (loads have had the whole S+softmax phase to land);
        // prefetch next K (lands during PV compute)
#pragma unroll
        for (int it = 0; it < 4; it++) {
            int idx = tid + it * 256;
            int r = idx >> 4, c4 = (idx & 15) << 2;
            *(float4*)&Vs[r * VST + c4] = cvt4(vreg[it]);
        }
        if (kt + 1 < L_SEQ / 64) {
#pragma unroll
            for (int it = 0; it < 4; it++) {
                int idx = tid + it * 256;
                int r = idx >> 4, c4 = (idx & 15) << 2;
                kreg[it] = *(const float4*)(kbase + (size_t)((kt + 1) * 64 + r) * QKV_COLS + c4);
            }
        }
        __syncthreads();   // Vs visible (Ps warp-private writes also done)

        // O += P @ V   (A = P warp rows, B = Vs[j][d] natural layout)
#pragma unroll
        for (int kb = 0; kb < 64; kb += 8) {
            uint32_t a0 = __float_as_uint(Ps[rlo * FST + kb + qid]);
            uint32_t a1 = __float_as_uint(Ps[(rlo + 8) * FST + kb + qid]);
            uint32_t a2 = __float_as_uint(Ps[rlo * FST + kb + qid + 4]);
            uint32_t a3 = __float_as_uint(Ps[(rlo + 8) * FST + kb + qid + 4]);
#pragma unroll
            for (int df = 0; df < 8; df++) {
                uint32_t b0 = __float_as_uint(Vs[(kb + qid) * VST + df * 8 + grp]);
                uint32_t b1 = __float_as_uint(Vs[(kb + qid + 4) * VST + df * 8 + grp]);
                mma8(o[df], a0, a1, a2, a3, b0, b1);
            }
        }
    }

    // epilogue
    float inv0 = 1.0f / l0, inv1 = 1.0f / l1;
    float* obase = g_att + (size_t)b * L_SEQ * DIM + h * DH;
    int row = qt * 128 + rlo;
#pragma unroll
    for (int df = 0; df < 8; df++) {
        int cl = df * 8 + 2 * qid;
        *(float2*)(obase + (size_t)row * DIM + cl) =
            make_float2(o[df][0] * inv0, o[df][1] * inv0);
        *(float2*)(obase + (size_t)(row + 8) * DIM + cl) =
            make_float2(o[df][2] * inv1, o[df][3] * inv1);
    }
}

// ---------------------------------------------------------------------------
extern "C" void kernel_launch(void* const* d_in, const int* in_sizes, int n_in,
                              void* d_out, int out_size)
{
    const float* x      = (const float*)d_in[0];
    const float* w_qkv  = (const float*)d_in[1];
    const float* w_proj = (const float*)d_in[2];
    const float* b_proj = (const float*)d_in[3];
    float* out = (float*)d_out;

    float *qkv_ptr, *att_ptr;
    cudaGetSymbolAddress((void**)&qkv_ptr, g_qkv);
    cudaGetSymbolAddress((void**)&att_ptr, g_att);

    cudaFuncSetAttribute(flash_tf32,
                         cudaFuncAttributeMaxDynamicSharedMemorySize, FLASH_SMEM);

    const int M = BATCH * L_SEQ;  // 4096

    pos_init<<<L_SEQ / 256, 256>>>();

    gemm_tf32<<<dim3(QKV_COLS / 128, M / 128), 256>>>(
        x, w_qkv, qkv_ptr, M, QKV_COLS, DIM, nullptr);

    flash_tf32<<<dim3(L_SEQ / 128, HEADS, BATCH), 256, FLASH_SMEM>>>();

    gemm_tf32<<<dim3(DIM / 128, M / 128), 256>>>(
        att_ptr, w_proj, out, M, DIM, DIM, b_proj);
}

// round 14
// speedup vs baseline: 2.8513x; 1.0413x over previous
#include <cuda_runtime.h>
#include <math.h>
#include <stdint.h>

#define BATCH   2
#define L_SEQ   2048
#define DIM     1024
#define HEADS   16
#define DH      64
#define QKV_COLS 3072
#define PHI_F   1.6180339887498949f
#define L2E     1.4426950408889634f

// Scratch (device globals: allocation-free rule)
__device__ float g_qkv[(size_t)BATCH * L_SEQ * QKV_COLS];  // ~50 MB
__device__ float g_att[(size_t)BATCH * L_SEQ * DIM];       // ~17 MB
__device__ float g_pos[L_SEQ];                             // phi positions * log2e

// ---------------------------------------------------------------------------
// helpers
// ---------------------------------------------------------------------------
__device__ __forceinline__ uint32_t f2tf32(float x) {
    uint32_t r;
    asm("cvt.rna.tf32.f32 %0, %1;" : "=r"(r) : "f"(x));
    return r;
}
__device__ __forceinline__ float4 cvt4(float4 v) {
    v.x = __uint_as_float(f2tf32(v.x));
    v.y = __uint_as_float(f2tf32(v.y));
    v.z = __uint_as_float(f2tf32(v.z));
    v.w = __uint_as_float(f2tf32(v.w));
    return v;
}
__device__ __forceinline__ float4 cvt4s(float4 v, float s) {
    v.x = __uint_as_float(f2tf32(v.x * s));
    v.y = __uint_as_float(f2tf32(v.y * s));
    v.z = __uint_as_float(f2tf32(v.z * s));
    v.w = __uint_as_float(f2tf32(v.w * s));
    return v;
}
__device__ __forceinline__ void mma8(float* c, uint32_t a0, uint32_t a1,
                                     uint32_t a2, uint32_t a3,
                                     uint32_t b0, uint32_t b1) {
    asm("mma.sync.aligned.m16n8k8.row.col.f32.tf32.tf32.f32 "
        "{%0,%1,%2,%3}, {%4,%5,%6,%7}, {%8,%9}, {%0,%1,%2,%3};"
        : "+f"(c[0]), "+f"(c[1]), "+f"(c[2]), "+f"(c[3])
        : "r"(a0), "r"(a1), "r"(a2), "r"(a3), "r"(b0), "r"(b1));
}
// 2^x on the FMA pipe (inputs in log2 domain; logits bounded ~[-10, 10])
__device__ __forceinline__ float fexp2(float x) {
    x = fmaxf(x, -126.0f);
    float n = rintf(x);
    float f = x - n;
    float p = 1.3333557e-3f;             // 2^f minimax, |f|<=0.5
    p = fmaf(p, f, 9.6181291e-3f);
    p = fmaf(p, f, 5.5504109e-2f);
    p = fmaf(p, f, 2.4022651e-1f);
    p = fmaf(p, f, 6.9314718e-1f);
    p = fmaf(p, f, 1.0f);
    int e = (int)n;
    return p * __int_as_float((e + 127) << 23);
}

// ---------------------------------------------------------------------------
// phi position table: g_pos[i] = fmodf(i*phi, 1) * log2(e)
// ---------------------------------------------------------------------------
__global__ void pos_init()
{
    int i = blockIdx.x * 256 + threadIdx.x;
    if (i < L_SEQ)
        g_pos[i] = fmodf((float)i * PHI_F, 1.0f) * L2E;
}

// ---------------------------------------------------------------------------
// tf32 mma GEMM: C[M,N] = A[M,K] @ B[K,N] (+bias). 128x128x16 tile,
// 256 thr (8 warps, 4x2), warp tile 32x64. (verified kernel, unchanged)
// ---------------------------------------------------------------------------
#define AST 20
#define BST 136

__global__ __launch_bounds__(256) void gemm_tf32(
    const float* __restrict__ A, const float* __restrict__ B,
    float* __restrict__ C, int M, int N, int K,
    const float* __restrict__ bias)
{
    __shared__ float As[128 * AST];
    __shared__ float Bs[16 * BST];

    const int tid = threadIdx.x;
    const int lane = tid & 31, wid = tid >> 5;
    const int wm = wid >> 1, wn = wid & 1;
    const int grp = lane >> 2, qid = lane & 3;
    const int row0 = blockIdx.y * 128;
    const int col0 = blockIdx.x * 128;

    float acc[2][8][4];
#pragma unroll
    for (int mf = 0; mf < 2; mf++)
#pragma unroll
        for (int nf = 0; nf < 8; nf++)
#pragma unroll
            for (int i = 0; i < 4; i++) acc[mf][nf][i] = 0.0f;

    const int ar0 = tid >> 2,  ac0 = (tid & 3) << 2;
    const int br0 = tid >> 5,  bc0 = (tid & 31) << 2;

    float4 pa[2], pb[2];
#pragma unroll
    for (int it = 0; it < 2; it++) {
        pa[it] = *(const float4*)(A + (size_t)(row0 + ar0 + it * 64) * K + ac0);
        pb[it] = *(const float4*)(B + (size_t)(br0 + it * 8) * N + col0 + bc0);
    }

    for (int k0 = 0; k0 < K; k0 += 16) {
#pragma unroll
        for (int it = 0; it < 2; it++) {
            *(float4*)&As[(ar0 + it * 64) * AST + ac0] = cvt4(pa[it]);
            *(float4*)&Bs[(br0 + it * 8) * BST + bc0] = cvt4(pb[it]);
        }
        __syncthreads();
        if (k0 + 16 < K) {
#pragma unroll
            for (int it = 0; it < 2; it++) {
                pa[it] = *(const float4*)(A + (size_t)(row0 + ar0 + it * 64) * K + k0 + 16 + ac0);
                pb[it] = *(const float4*)(B + (size_t)(k0 + 16 + br0 + it * 8) * N + col0 + bc0);
            }
        }
#pragma unroll
        for (int ks = 0; ks < 2; ks++) {
            const int kb = ks * 8;
            uint32_t a[2][4];
#pragma unroll
            for (int mf = 0; mf < 2; mf++) {
                int r = wm * 32 + mf * 16 + grp;
                a[mf][0] = __float_as_uint(As[r * AST + kb + qid]);
                a[mf][1] = __float_as_uint(As[(r + 8) * AST + kb + qid]);
                a[mf][2] = __float_as_uint(As[r * AST + kb + qid + 4]);
                a[mf][3] = __float_as_uint(As[(r + 8) * AST + kb + qid + 4]);
            }
#pragma unroll
            for (int nf = 0; nf < 8; nf++) {
                int n = wn * 64 + nf * 8 + grp;
                uint32_t b0 = __float_as_uint(Bs[(kb + qid) * BST + n]);
                uint32_t b1 = __float_as_uint(Bs[(kb + qid + 4) * BST + n]);
                mma8(acc[0][nf], a[0][0], a[0][1], a[0][2], a[0][3], b0, b1);
                mma8(acc[1][nf], a[1][0], a[1][1], a[1][2], a[1][3], b0, b1);
            }
        }
        __syncthreads();
    }

#pragma unroll
    for (int mf = 0; mf < 2; mf++) {
#pragma unroll
        for (int nf = 0; nf < 8; nf++) {
            int r = row0 + wm * 32 + mf * 16 + grp;
            int c = col0 + wn * 64 + nf * 8 + 2 * qid;
            float b0v = bias ? bias[c] : 0.0f;
            float b1v = bias ? bias[c + 1] : 0.0f;
            float2 lo = make_float2(acc[mf][nf][0] + b0v, acc[mf][nf][1] + b1v);
            float2 hi = make_float2(acc[mf][nf][2] + b0v, acc[mf][nf][3] + b1v);
            *(float2*)(C + (size_t)r * N + c) = lo;
            *(float2*)(C + (size_t)(r + 8) * N + c) = hi;
        }
    }
}

// ---------------------------------------------------------------------------
// Flash attention on tf32 mma. BM=128, BN=64, Dh=64.
// Grid (L/128, HEADS, BATCH), 256 thr (8 warps); warp owns 16 q rows.
// Round-14: static softmax shift (logits provably bounded) -- no running max,
// no O-rescale, l-reduction deferred to epilogue; 2 syncthreads/iter.
// ---------------------------------------------------------------------------
#define FST 68
#define VST 72
#define FLASH_SMEM ((128 * FST + 64 * FST + 128 * FST + 64 * VST) * 4)

__global__ __launch_bounds__(256, 2) void flash_tf32()
{
    extern __shared__ float sm[];
    float* Qs = sm;                    // [128][68]
    float* Ks = Qs + 128 * FST;        // [64][68]
    float* Ps = Ks + 64 * FST;         // [128][68]
    float* Vs = Ps + 128 * FST;        // [64][72]  natural V[j][d]

    const int qt = blockIdx.x, h = blockIdx.y, b = blockIdx.z;
    const int tid = threadIdx.x, lane = tid & 31, w = tid >> 5;
    const int grp = lane >> 2, qid = lane & 3;

    const float* qbase = g_qkv + (size_t)b * L_SEQ * QKV_COLS + h * DH;
    const float* kbase = qbase + DIM;
    const float* vbase = qbase + 2 * DIM;

    const float QSCL = 0.125f * L2E;   // folded softmax scale (pre-rounding)

    // load Q tile: 128 rows, scaled, cvt tf32
#pragma unroll
    for (int it = 0; it < 8; it++) {
        int idx = tid + it * 256;
        int r = idx >> 4, c4 = (idx & 15) << 2;
        float4 v = *(const float4*)(qbase + (size_t)(qt * 128 + r) * QKV_COLS + c4);
        *(float4*)&Qs[r * FST + c4] = cvt4s(v, QSCL);
    }

    const int rlo = w * 16 + grp;
    const float pq0 = g_pos[qt * 128 + rlo];
    const float pq1 = g_pos[qt * 128 + rlo + 8];

    float l0 = 0.0f, l1 = 0.0f;        // per-thread partial row sums
    float o[8][4];
#pragma unroll
    for (int df = 0; df < 8; df++)
#pragma unroll
        for (int i = 0; i < 4; i++) o[df][i] = 0.0f;

    // K prefetch for tile 0
    float4 kreg[4], vreg[4];
#pragma unroll
    for (int it = 0; it < 4; it++) {
        int idx = tid + it * 256;
        int r = idx >> 4, c4 = (idx & 15) << 2;
        kreg[it] = *(const float4*)(kbase + (size_t)r * QKV_COLS + c4);
    }
    __syncthreads();   // Qs visible before first S-phase

    for (int kt = 0; kt < L_SEQ / 64; kt++) {
        // store prefetched K (safe: post-V sync of prev iter guarantees all
        // S-phase Ks reads done; PV never reads Ks); issue V loads
#pragma unroll
        for (int it = 0; it < 4; it++) {
            int idx = tid + it * 256;
            int r = idx >> 4, c4 = (idx & 15) << 2;
            *(float4*)&Ks[r * FST + c4] = cvt4(kreg[it]);
            vreg[it] = *(const float4*)(vbase + (size_t)(kt * 64 + r) * QKV_COLS + c4);
        }
        __syncthreads();   // Ks visible; all prev-iter PV Vs reads complete

        // S = Q @ K^T  (warp: 16 x 64), log2 units
        float s[8][4];
#pragma unroll
        for (int nf = 0; nf < 8; nf++)
#pragma unroll
            for (int i = 0; i < 4; i++) s[nf][i] = 0.0f;
#pragma unroll
        for (int kb = 0; kb < 64; kb += 8) {
            uint32_t a0 = __float_as_uint(Qs[rlo * FST + kb + qid]);
            uint32_t a1 = __float_as_uint(Qs[(rlo + 8) * FST + kb + qid]);
            uint32_t a2 = __float_as_uint(Qs[rlo * FST + kb + qid + 4]);
            uint32_t a3 = __float_as_uint(Qs[(rlo + 8) * FST + kb + qid + 4]);
#pragma unroll
            for (int nf = 0; nf < 8; nf++) {
                uint32_t b0 = __float_as_uint(Ks[(nf * 8 + grp) * FST + kb + qid]);
                uint32_t b1 = __float_as_uint(Ks[(nf * 8 + grp) * FST + kb + qid + 4]);
                mma8(s[nf], a0, a1, a2, a3, b0, b1);
            }
        }

        // p = 2^(s - |pq - pk|); accumulate partial sums; store P
#pragma unroll
        for (int nf = 0; nf < 8; nf++) {
            float pk0 = g_pos[kt * 64 + nf * 8 + 2 * qid];
            float pk1 = g_pos[kt * 64 + nf * 8 + 2 * qid + 1];
            float p00 = fexp2(s[nf][0] - fabsf(pq0 - pk0));
            float p01 = fexp2(s[nf][1] - fabsf(pq0 - pk1));
            float p10 = fexp2(s[nf][2] - fabsf(pq1 - pk0));
            float p11 = fexp2(s[nf][3] - fabsf(pq1 - pk1));
            l0 += p00 + p01; l1 += p10 + p11;
            int cl = nf * 8 + 2 * qid;
            *(float2*)&Ps[rlo * FST + cl] =
                make_float2(__uint_as_float(f2tf32(p00)), __uint_as_float(f2tf32(p01)));
            *(float2*)&Ps[(rlo + 8) * FST + cl] =
                make_float2(__uint_as_float(f2tf32(p10)), __uint_as_float(f2tf32(p11)));
        }

        // store V (loads had the whole S+softmax phase to land);
        // prefetch next K (lands during PV compute)
#pragma unroll
        for (int it = 0; it < 4; it++) {
            int idx = tid + it * 256;
            int r = idx >> 4, c4 = (idx & 15) << 2;
            *(float4*)&Vs[r * VST + c4] = cvt4(vreg[it]);
        }
        if (kt + 1 < L_SEQ / 64) {
#pragma unroll
            for (int it = 0; it < 4; it++) {
                int idx = tid + it * 256;
                int r = idx >> 4, c4 = (idx & 15) << 2;
                kreg[it] = *(const float4*)(kbase + (size_t)((kt + 1) * 64 + r) * QKV_COLS + c4);
            }
        }
        __syncthreads();   // Vs visible (Ps warp-private writes also done)

        // O += P @ V   (A = P warp rows, B = Vs[j][d] natural layout)
#pragma unroll
        for (int kb = 0; kb < 64; kb += 8) {
            uint32_t a0 = __float_as_uint(Ps[rlo * FST + kb + qid]);
            uint32_t a1 = __float_as_uint(Ps[(rlo + 8) * FST + kb + qid]);
            uint32_t a2 = __float_as_uint(Ps[rlo * FST + kb + qid + 4]);
            uint32_t a3 = __float_as_uint(Ps[(rlo + 8) * FST + kb + qid + 4]);
#pragma unroll
            for (int df = 0; df < 8; df++) {
                uint32_t b0 = __float_as_uint(Vs[(kb + qid) * VST + df * 8 + grp]);
                uint32_t b1 = __float_as_uint(Vs[(kb + qid + 4) * VST + df * 8 + grp]);
                mma8(o[df], a0, a1, a2, a3, b0, b1);
            }
        }
    }

    // epilogue: reduce row sums across the 4 qid lanes, normalize, store
    l0 += __shfl_xor_sync(0xffffffffu, l0, 1);
    l0 += __shfl_xor_sync(0xffffffffu, l0, 2);
    l1 += __shfl_xor_sync(0xffffffffu, l1, 1);
    l1 += __shfl_xor_sync(0xffffffffu, l1, 2);
    float inv0 = 1.0f / l0, inv1 = 1.0f / l1;
    float* obase = g_att + (size_t)b * L_SEQ * DIM + h * DH;
    int row = qt * 128 + rlo;
#pragma unroll
    for (int df = 0; df < 8; df++) {
        int cl = df * 8 + 2 * qid;
        *(float2*)(obase + (size_t)row * DIM + cl) =
            make_float2(o[df][0] * inv0, o[df][1] * inv0);
        *(float2*)(obase + (size_t)(row + 8) * DIM + cl) =
            make_float2(o[df][2] * inv1, o[df][3] * inv1);
    }
}

// ---------------------------------------------------------------------------
extern "C" void kernel_launch(void* const* d_in, const int* in_sizes, int n_in,
                              void* d_out, int out_size)
{
    const float* x      = (const float*)d_in[0];
    const float* w_qkv  = (const float*)d_in[1];
    const float* w_proj = (const float*)d_in[2];
    const float* b_proj = (const float*)d_in[3];
    float* out = (float*)d_out;

    float *qkv_ptr, *att_ptr;
    cudaGetSymbolAddress((void**)&qkv_ptr, g_qkv);
    cudaGetSymbolAddress((void**)&att_ptr, g_att);

    cudaFuncSetAttribute(flash_tf32,
                         cudaFuncAttributeMaxDynamicSharedMemorySize, FLASH_SMEM);

    const int M = BATCH * L_SEQ;  // 4096

    pos_init<<<L_SEQ / 256, 256>>>();

    gemm_tf32<<<dim3(QKV_COLS / 128, M / 128), 256>>>(
        x, w_qkv, qkv_ptr, M, QKV_COLS, DIM, nullptr);

    flash_tf32<<<dim3(L_SEQ / 128, HEADS, BATCH), 256, FLASH_SMEM>>>();

    gemm_tf32<<<dim3(DIM / 128, M / 128), 256>>>(
        att_ptr, w_proj, out, M, DIM, DIM, b_proj);
}

// round 16
// speedup vs baseline: 3.0376x; 1.0653x over previous
#include <cuda_runtime.h>
#include <math.h>
#include <stdint.h>

#define BATCH   2
#define L_SEQ   2048
#define DIM     1024
#define HEADS   16
#define DH      64
#define QKV_COLS 3072
#define PHI_F   1.6180339887498949f
#define L2E     1.4426950408889634f

// Scratch (device globals: allocation-free rule)
__device__ float g_qkv[(size_t)BATCH * L_SEQ * QKV_COLS];  // ~50 MB
__device__ float g_att[(size_t)BATCH * L_SEQ * DIM];       // ~17 MB
__device__ float g_pos[L_SEQ];                             // phi positions * log2e

// ---------------------------------------------------------------------------
// helpers
// ---------------------------------------------------------------------------
__device__ __forceinline__ uint32_t f2tf32(float x) {
    uint32_t r;
    asm("cvt.rna.tf32.f32 %0, %1;" : "=r"(r) : "f"(x));
    return r;
}
__device__ __forceinline__ float4 cvt4(float4 v) {
    v.x = __uint_as_float(f2tf32(v.x));
    v.y = __uint_as_float(f2tf32(v.y));
    v.z = __uint_as_float(f2tf32(v.z));
    v.w = __uint_as_float(f2tf32(v.w));
    return v;
}
__device__ __forceinline__ float4 cvt4s(float4 v, float s) {
    v.x = __uint_as_float(f2tf32(v.x * s));
    v.y = __uint_as_float(f2tf32(v.y * s));
    v.z = __uint_as_float(f2tf32(v.z * s));
    v.w = __uint_as_float(f2tf32(v.w * s));
    return v;
}
__device__ __forceinline__ void mma8(float* c, uint32_t a0, uint32_t a1,
                                     uint32_t a2, uint32_t a3,
                                     uint32_t b0, uint32_t b1) {
    asm("mma.sync.aligned.m16n8k8.row.col.f32.tf32.tf32.f32 "
        "{%0,%1,%2,%3}, {%4,%5,%6,%7}, {%8,%9}, {%0,%1,%2,%3};"
        : "+f"(c[0]), "+f"(c[1]), "+f"(c[2]), "+f"(c[3])
        : "r"(a0), "r"(a1), "r"(a2), "r"(a3), "r"(b0), "r"(b1));
}
// MUFU exp2: single SASS MUFU.EX2 (rt 8/SMSP), logits bounded so no clamp needed
__device__ __forceinline__ float ex2_approx(float x) {
    float r;
    asm("ex2.approx.ftz.f32 %0, %1;" : "=f"(r) : "f"(x));
    return r;
}

// ---------------------------------------------------------------------------
// phi position table: g_pos[i] = fmodf(i*phi, 1) * log2(e)
// ---------------------------------------------------------------------------
__global__ void pos_init()
{
    int i = blockIdx.x * 256 + threadIdx.x;
    if (i < L_SEQ)
        g_pos[i] = fmodf((float)i * PHI_F, 1.0f) * L2E;
}

// ---------------------------------------------------------------------------
// tf32 mma GEMM: C[M,N] = A[M,K] @ B[K,N] (+bias). 128x128x16 tile,
// 256 thr (8 warps, 4x2), warp tile 32x64. (verified kernel, unchanged)
// ---------------------------------------------------------------------------
#define AST 20
#define BST 136

__global__ __launch_bounds__(256) void gemm_tf32(
    const float* __restrict__ A, const float* __restrict__ B,
    float* __restrict__ C, int M, int N, int K,
    const float* __restrict__ bias)
{
    __shared__ float As[128 * AST];
    __shared__ float Bs[16 * BST];

    const int tid = threadIdx.x;
    const int lane = tid & 31, wid = tid >> 5;
    const int wm = wid >> 1, wn = wid & 1;
    const int grp = lane >> 2, qid = lane & 3;
    const int row0 = blockIdx.y * 128;
    const int col0 = blockIdx.x * 128;

    float acc[2][8][4];
#pragma unroll
    for (int mf = 0; mf < 2; mf++)
#pragma unroll
        for (int nf = 0; nf < 8; nf++)
#pragma unroll
            for (int i = 0; i < 4; i++) acc[mf][nf][i] = 0.0f;

    const int ar0 = tid >> 2,  ac0 = (tid & 3) << 2;
    const int br0 = tid >> 5,  bc0 = (tid & 31) << 2;

    float4 pa[2], pb[2];
#pragma unroll
    for (int it = 0; it < 2; it++) {
        pa[it] = *(const float4*)(A + (size_t)(row0 + ar0 + it * 64) * K + ac0);
        pb[it] = *(const float4*)(B + (size_t)(br0 + it * 8) * N + col0 + bc0);
    }

    for (int k0 = 0; k0 < K; k0 += 16) {
#pragma unroll
        for (int it = 0; it < 2; it++) {
            *(float4*)&As[(ar0 + it * 64) * AST + ac0] = cvt4(pa[it]);
            *(float4*)&Bs[(br0 + it * 8) * BST + bc0] = cvt4(pb[it]);
        }
        __syncthreads();
        if (k0 + 16 < K) {
#pragma unroll
            for (int it = 0; it < 2; it++) {
                pa[it] = *(const float4*)(A + (size_t)(row0 + ar0 + it * 64) * K + k0 + 16 + ac0);
                pb[it] = *(const float4*)(B + (size_t)(k0 + 16 + br0 + it * 8) * N + col0 + bc0);
            }
        }
#pragma unroll
        for (int ks = 0; ks < 2; ks++) {
            const int kb = ks * 8;
            uint32_t a[2][4];
#pragma unroll
            for (int mf = 0; mf < 2; mf++) {
                int r = wm * 32 + mf * 16 + grp;
                a[mf][0] = __float_as_uint(As[r * AST + kb + qid]);
                a[mf][1] = __float_as_uint(As[(r + 8) * AST + kb + qid]);
                a[mf][2] = __float_as_uint(As[r * AST + kb + qid + 4]);
                a[mf][3] = __float_as_uint(As[(r + 8) * AST + kb + qid + 4]);
            }
#pragma unroll
            for (int nf = 0; nf < 8; nf++) {
                int n = wn * 64 + nf * 8 + grp;
                uint32_t b0 = __float_as_uint(Bs[(kb + qid) * BST + n]);
                uint32_t b1 = __float_as_uint(Bs[(kb + qid + 4) * BST + n]);
                mma8(acc[0][nf], a[0][0], a[0][1], a[0][2], a[0][3], b0, b1);
                mma8(acc[1][nf], a[1][0], a[1][1], a[1][2], a[1][3], b0, b1);
            }
        }
        __syncthreads();
    }

#pragma unroll
    for (int mf = 0; mf < 2; mf++) {
#pragma unroll
        for (int nf = 0; nf < 8; nf++) {
            int r = row0 + wm * 32 + mf * 16 + grp;
            int c = col0 + wn * 64 + nf * 8 + 2 * qid;
            float b0v = bias ? bias[c] : 0.0f;
            float b1v = bias ? bias[c + 1] : 0.0f;
            float2 lo = make_float2(acc[mf][nf][0] + b0v, acc[mf][nf][1] + b1v);
            float2 hi = make_float2(acc[mf][nf][2] + b0v, acc[mf][nf][3] + b1v);
            *(float2*)(C + (size_t)r * N + c) = lo;
            *(float2*)(C + (size_t)(r + 8) * N + c) = hi;
        }
    }
}

// ---------------------------------------------------------------------------
// Flash attention on tf32 mma. BM=128, BN=64, Dh=64.
// Grid (L/128, HEADS, BATCH), 256 thr (8 warps); warp owns 16 q rows.
// Round-16: softmax exp via MUFU ex2.approx (inline PTX) -- at 1 exp/element
// the hardware unit (rt 8/SMSP) beats the 10-instr FMA-pipe polynomial 2.5x.
// Static shift (logits provably bounded), deferred l-reduction, 2 syncs/iter.
// ---------------------------------------------------------------------------
#define FST 68
#define VST 72
#define FLASH_SMEM ((128 * FST + 64 * FST + 128 * FST + 64 * VST) * 4)

__global__ __launch_bounds__(256, 2) void flash_tf32()
{
    extern __shared__ float sm[];
    float* Qs = sm;                    // [128][68]
    float* Ks = Qs + 128 * FST;        // [64][68]
    float* Ps = Ks + 64 * FST;         // [128][68]
    float* Vs = Ps + 128 * FST;        // [64][72]  natural V[j][d]

    const int qt = blockIdx.x, h = blockIdx.y, b = blockIdx.z;
    const int tid = threadIdx.x, lane = tid & 31, w = tid >> 5;
    const int grp = lane >> 2, qid = lane & 3;

    const float* qbase = g_qkv + (size_t)b * L_SEQ * QKV_COLS + h * DH;
    const float* kbase = qbase + DIM;
    const float* vbase = qbase + 2 * DIM;

    const float QSCL = 0.125f * L2E;   // folded softmax scale (pre-rounding)

    // load Q tile: 128 rows, scaled, cvt tf32
#pragma unroll
    for (int it = 0; it < 8; it++) {
        int idx = tid + it * 256;
        int r = idx >> 4, c4 = (idx & 15) << 2;
        float4 v = *(const float4*)(qbase + (size_t)(qt * 128 + r) * QKV_COLS + c4);
        *(float4*)&Qs[r * FST + c4] = cvt4s(v, QSCL);
    }

    const int rlo = w * 16 + grp;
    const float pq0 = g_pos[qt * 128 + rlo];
    const float pq1 = g_pos[qt * 128 + rlo + 8];

    float l0 = 0.0f, l1 = 0.0f;        // per-thread partial row sums
    float o[8][4];
#pragma unroll
    for (int df = 0; df < 8; df++)
#pragma unroll
        for (int i = 0; i < 4; i++) o[df][i] = 0.0f;

    // K prefetch for tile 0
    float4 kreg[4], vreg[4];
#pragma unroll
    for (int it = 0; it < 4; it++) {
        int idx = tid + it * 256;
        int r = idx >> 4, c4 = (idx & 15) << 2;
        kreg[it] = *(const float4*)(kbase + (size_t)r * QKV_COLS + c4);
    }
    __syncthreads();   // Qs visible before first S-phase

    for (int kt = 0; kt < L_SEQ / 64; kt++) {
        // store prefetched K (safe: post-V sync of prev iter guarantees all
        // S-phase Ks reads done; PV never reads Ks); issue V loads
#pragma unroll
        for (int it = 0; it < 4; it++) {
            int idx = tid + it * 256;
            int r = idx >> 4, c4 = (idx & 15) << 2;
            *(float4*)&Ks[r * FST + c4] = cvt4(kreg[it]);
            vreg[it] = *(const float4*)(vbase + (size_t)(kt * 64 + r) * QKV_COLS + c4);
        }
        __syncthreads();   // Ks visible; all prev-iter PV Vs reads complete

        // S = Q @ K^T  (warp: 16 x 64), log2 units
        float s[8][4];
#pragma unroll
        for (int nf = 0; nf < 8; nf++)
#pragma unroll
            for (int i = 0; i < 4; i++) s[nf][i] = 0.0f;
#pragma unroll
        for (int kb = 0; kb < 64; kb += 8) {
            uint32_t a0 = __float_as_uint(Qs[rlo * FST + kb + qid]);
            uint32_t a1 = __float_as_uint(Qs[(rlo + 8) * FST + kb + qid]);
            uint32_t a2 = __float_as_uint(Qs[rlo * FST + kb + qid + 4]);
            uint32_t a3 = __float_as_uint(Qs[(rlo + 8) * FST + kb + qid + 4]);
#pragma unroll
            for (int nf = 0; nf < 8; nf++) {
                uint32_t b0 = __float_as_uint(Ks[(nf * 8 + grp) * FST + kb + qid]);
                uint32_t b1 = __float_as_uint(Ks[(nf * 8 + grp) * FST + kb + qid + 4]);
                mma8(s[nf], a0, a1, a2, a3, b0, b1);
            }
        }

        // p = 2^(s - |pq - pk|) via MUFU; accumulate partial sums; store P
#pragma unroll
        for (int nf = 0; nf < 8; nf++) {
            float pk0 = g_pos[kt * 64 + nf * 8 + 2 * qid];
            float pk1 = g_pos[kt * 64 + nf * 8 + 2 * qid + 1];
            float p00 = ex2_approx(s[nf][0] - fabsf(pq0 - pk0));
            float p01 = ex2_approx(s[nf][1] - fabsf(pq0 - pk1));
            float p10 = ex2_approx(s[nf][2] - fabsf(pq1 - pk0));
            float p11 = ex2_approx(s[nf][3] - fabsf(pq1 - pk1));
            l0 += p00 + p01; l1 += p10 + p11;
            int cl = nf * 8 + 2 * qid;
            *(float2*)&Ps[rlo * FST + cl] =
                make_float2(__uint_as_float(f2tf32(p00)), __uint_as_float(f2tf32(p01)));
            *(float2*)&Ps[(rlo + 8) * FST + cl] =
                make_float2(__uint_as_float(f2tf32(p10)), __uint_as_float(f2tf32(p11)));
        }

        // store V (loads had the whole S+softmax phase to land);
        // prefetch next K (lands during PV compute)
#pragma unroll
        for (int it = 0; it < 4; it++) {
            int idx = tid + it * 256;
            int r = idx >> 4, c4 = (idx & 15) << 2;
            *(float4*)&Vs[r * VST + c4] = cvt4(vreg[it]);
        }
        if (kt + 1 < L_SEQ / 64) {
#pragma unroll
            for (int it = 0; it < 4; it++) {
                int idx = tid + it * 256;
                int r = idx >> 4, c4 = (idx & 15) << 2;
                kreg[it] = *(const float4*)(kbase + (size_t)((kt + 1) * 64 + r) * QKV_COLS + c4);
            }
        }
        __syncthreads();   // Vs visible (Ps warp-private writes also done)

        // O += P @ V   (A = P warp rows, B = Vs[j][d] natural layout)
#pragma unroll
        for (int kb = 0; kb < 64; kb += 8) {
            uint32_t a0 = __float_as_uint(Ps[rlo * FST + kb + qid]);
            uint32_t a1 = __float_as_uint(Ps[(rlo + 8) * FST + kb + qid]);
            uint32_t a2 = __float_as_uint(Ps[rlo * FST + kb + qid + 4]);
            uint32_t a3 = __float_as_uint(Ps[(rlo + 8) * FST + kb + qid + 4]);
#pragma unroll
            for (int df = 0; df < 8; df++) {
                uint32_t b0 = __float_as_uint(Vs[(kb + qid) * VST + df * 8 + grp]);
                uint32_t b1 = __float_as_uint(Vs[(kb + qid + 4) * VST + df * 8 + grp]);
                mma8(o[df], a0, a1, a2, a3, b0, b1);
            }
        }
    }

    // epilogue: reduce row sums across the 4 qid lanes, normalize, store
    l0 += __shfl_xor_sync(0xffffffffu, l0, 1);
    l0 += __shfl_xor_sync(0xffffffffu, l0, 2);
    l1 += __shfl_xor_sync(0xffffffffu, l1, 1);
    l1 += __shfl_xor_sync(0xffffffffu, l1, 2);
    float inv0 = 1.0f / l0, inv1 = 1.0f / l1;
    float* obase = g_att + (size_t)b * L_SEQ * DIM + h * DH;
    int row = qt * 128 + rlo;
#pragma unroll
    for (int df = 0; df < 8; df++) {
        int cl = df * 8 + 2 * qid;
        *(float2*)(obase + (size_t)row * DIM + cl) =
            make_float2(o[df][0] * inv0, o[df][1] * inv0);
        *(float2*)(obase + (size_t)(row + 8) * DIM + cl) =
            make_float2(o[df][2] * inv1, o[df][3] * inv1);
    }
}

// ---------------------------------------------------------------------------
extern "C" void kernel_launch(void* const* d_in, const int* in_sizes, int n_in,
                              void* d_out, int out_size)
{
    const float* x      = (const float*)d_in[0];
    const float* w_qkv  = (const float*)d_in[1];
    const float* w_proj = (const float*)d_in[2];
    const float* b_proj = (const float*)d_in[3];
    float* out = (float*)d_out;

    float *qkv_ptr, *att_ptr;
    cudaGetSymbolAddress((void**)&qkv_ptr, g_qkv);
    cudaGetSymbolAddress((void**)&att_ptr, g_att);

    cudaFuncSetAttribute(flash_tf32,
                         cudaFuncAttributeMaxDynamicSharedMemorySize, FLASH_SMEM);

    const int M = BATCH * L_SEQ;  // 4096

    pos_init<<<L_SEQ / 256, 256>>>();

    gemm_tf32<<<dim3(QKV_COLS / 128, M / 128), 256>>>(
        x, w_qkv, qkv_ptr, M, QKV_COLS, DIM, nullptr);

    flash_tf32<<<dim3(L_SEQ / 128, HEADS, BATCH), 256, FLASH_SMEM>>>();

    gemm_tf32<<<dim3(DIM / 128, M / 128), 256>>>(
        att_ptr, w_proj, out, M, DIM, DIM, b_proj);
}

// round 17
// speedup vs baseline: 3.8807x; 1.2775x over previous
#include <cuda_runtime.h>
#include <cuda_fp16.h>
#include <math.h>
#include <stdint.h>

#define BATCH   2
#define L_SEQ   2048
#define DIM     1024
#define HEADS   16
#define DH      64
#define QKV_COLS 3072
#define PHI_F   1.6180339887498949f
#define L2E     1.4426950408889634f

// Scratch (device globals: allocation-free rule)
__device__ float g_qkv[(size_t)BATCH * L_SEQ * QKV_COLS];  // ~50 MB
__device__ float g_att[(size_t)BATCH * L_SEQ * DIM];       // ~17 MB
__device__ float g_pos[L_SEQ];                             // phi positions * log2e

// ---------------------------------------------------------------------------
// helpers
// ---------------------------------------------------------------------------
__device__ __forceinline__ uint32_t f2tf32(float x) {
    uint32_t r;
    asm("cvt.rna.tf32.f32 %0, %1;" : "=r"(r) : "f"(x));
    return r;
}
__device__ __forceinline__ float4 cvt4(float4 v) {
    v.x = __uint_as_float(f2tf32(v.x));
    v.y = __uint_as_float(f2tf32(v.y));
    v.z = __uint_as_float(f2tf32(v.z));
    v.w = __uint_as_float(f2tf32(v.w));
    return v;
}
__device__ __forceinline__ uint32_t pack_h2(float lo, float hi) {
    __half2 h = __floats2half2_rn(lo, hi);   // low 16 bits = lo, high = hi
    return *(uint32_t*)&h;
}
__device__ __forceinline__ void mma8(float* c, uint32_t a0, uint32_t a1,
                                     uint32_t a2, uint32_t a3,
                                     uint32_t b0, uint32_t b1) {
    asm("mma.sync.aligned.m16n8k8.row.col.f32.tf32.tf32.f32 "
        "{%0,%1,%2,%3}, {%4,%5,%6,%7}, {%8,%9}, {%0,%1,%2,%3};"
        : "+f"(c[0]), "+f"(c[1]), "+f"(c[2]), "+f"(c[3])
        : "r"(a0), "r"(a1), "r"(a2), "r"(a3), "r"(b0), "r"(b1));
}
// fp16 mma: same 10-bit mantissa as tf32, 2x the MAC rate, k=16 per instr
__device__ __forceinline__ void mma16(float* c, uint32_t a0, uint32_t a1,
                                      uint32_t a2, uint32_t a3,
                                      uint32_t b0, uint32_t b1) {
    asm("mma.sync.aligned.m16n8k16.row.col.f32.f16.f16.f32 "
        "{%0,%1,%2,%3}, {%4,%5,%6,%7}, {%8,%9}, {%0,%1,%2,%3};"
        : "+f"(c[0]), "+f"(c[1]), "+f"(c[2]), "+f"(c[3])
        : "r"(a0), "r"(a1), "r"(a2), "r"(a3), "r"(b0), "r"(b1));
}
// MUFU exp2: single SASS MUFU.EX2 (rt 8/SMSP)
__device__ __forceinline__ float ex2_approx(float x) {
    float r;
    asm("ex2.approx.ftz.f32 %0, %1;" : "=f"(r) : "f"(x));
    return r;
}

// ---------------------------------------------------------------------------
// phi position table: g_pos[i] = fmodf(i*phi, 1) * log2(e)
// ---------------------------------------------------------------------------
__global__ void pos_init()
{
    int i = blockIdx.x * 256 + threadIdx.x;
    if (i < L_SEQ)
        g_pos[i] = fmodf((float)i * PHI_F, 1.0f) * L2E;
}

// ---------------------------------------------------------------------------
// tf32 mma GEMM: C[M,N] = A[M,K] @ B[K,N] (+bias). 128x128x16 tile,
// 256 thr (8 warps, 4x2), warp tile 32x64. (verified kernel, unchanged)
// ---------------------------------------------------------------------------
#define AST 20
#define BST 136

__global__ __launch_bounds__(256) void gemm_tf32(
    const float* __restrict__ A, const float* __restrict__ B,
    float* __restrict__ C, int M, int N, int K,
    const float* __restrict__ bias)
{
    __shared__ float As[128 * AST];
    __shared__ float Bs[16 * BST];

    const int tid = threadIdx.x;
    const int lane = tid & 31, wid = tid >> 5;
    const int wm = wid >> 1, wn = wid & 1;
    const int grp = lane >> 2, qid = lane & 3;
    const int row0 = blockIdx.y * 128;
    const int col0 = blockIdx.x * 128;

    float acc[2][8][4];
#pragma unroll
    for (int mf = 0; mf < 2; mf++)
#pragma unroll
        for (int nf = 0; nf < 8; nf++)
#pragma unroll
            for (int i = 0; i < 4; i++) acc[mf][nf][i] = 0.0f;

    const int ar0 = tid >> 2,  ac0 = (tid & 3) << 2;
    const int br0 = tid >> 5,  bc0 = (tid & 31) << 2;

    float4 pa[2], pb[2];
#pragma unroll
    for (int it = 0; it < 2; it++) {
        pa[it] = *(const float4*)(A + (size_t)(row0 + ar0 + it * 64) * K + ac0);
        pb[it] = *(const float4*)(B + (size_t)(br0 + it * 8) * N + col0 + bc0);
    }

    for (int k0 = 0; k0 < K; k0 += 16) {
#pragma unroll
        for (int it = 0; it < 2; it++) {
            *(float4*)&As[(ar0 + it * 64) * AST + ac0] = cvt4(pa[it]);
            *(float4*)&Bs[(br0 + it * 8) * BST + bc0] = cvt4(pb[it]);
        }
        __syncthreads();
        if (k0 + 16 < K) {
#pragma unroll
            for (int it = 0; it < 2; it++) {
                pa[it] = *(const float4*)(A + (size_t)(row0 + ar0 + it * 64) * K + k0 + 16 + ac0);
                pb[it] = *(const float4*)(B + (size_t)(k0 + 16 + br0 + it * 8) * N + col0 + bc0);
            }
        }
#pragma unroll
        for (int ks = 0; ks < 2; ks++) {
            const int kb = ks * 8;
            uint32_t a[2][4];
#pragma unroll
            for (int mf = 0; mf < 2; mf++) {
                int r = wm * 32 + mf * 16 + grp;
                a[mf][0] = __float_as_uint(As[r * AST + kb + qid]);
                a[mf][1] = __float_as_uint(As[(r + 8) * AST + kb + qid]);
                a[mf][2] = __float_as_uint(As[r * AST + kb + qid + 4]);
                a[mf][3] = __float_as_uint(As[(r + 8) * AST + kb + qid + 4]);
            }
#pragma unroll
            for (int nf = 0; nf < 8; nf++) {
                int n = wn * 64 + nf * 8 + grp;
                uint32_t b0 = __float_as_uint(Bs[(kb + qid) * BST + n]);
                uint32_t b1 = __float_as_uint(Bs[(kb + qid + 4) * BST + n]);
                mma8(acc[0][nf], a[0][0], a[0][1], a[0][2], a[0][3], b0, b1);
                mma8(acc[1][nf], a[1][0], a[1][1], a[1][2], a[1][3], b0, b1);
            }
        }
        __syncthreads();
    }

#pragma unroll
    for (int mf = 0; mf < 2; mf++) {
#pragma unroll
        for (int nf = 0; nf < 8; nf++) {
            int r = row0 + wm * 32 + mf * 16 + grp;
            int c = col0 + wn * 64 + nf * 8 + 2 * qid;
            float b0v = bias ? bias[c] : 0.0f;
            float b1v = bias ? bias[c + 1] : 0.0f;
            float2 lo = make_float2(acc[mf][nf][0] + b0v, acc[mf][nf][1] + b1v);
            float2 hi = make_float2(acc[mf][nf][2] + b0v, acc[mf][nf][3] + b1v);
            *(float2*)(C + (size_t)r * N + c) = lo;
            *(float2*)(C + (size_t)(r + 8) * N + c) = hi;
        }
    }
}

// ---------------------------------------------------------------------------
// Flash attention on fp16 mma (m16n8k16). BM=128, BN=64, Dh=64.
// Grid (L/128, HEADS, BATCH), 256 thr (8 warps); warp owns 16 q rows.
// fp16 mantissa == tf32 mantissa -> same precision, 2x mma rate, half the
// instructions. All operands f16x2-packed along k:
//   Qs/Ks/Ps: [rows][36 u32] (32 data + 4 pad; banks 4*grp+qid distinct)
//   Vs: [32 j-pairs][72 u32] (paired-row LDG.64 loads pack j-pairs directly)
// P pack is natural: S-accumulator holds (2qid, 2qid+1) = a k-pair for PV.
// ---------------------------------------------------------------------------
#define QST 36
#define VST2 72
#define FLASH_SMEM16 ((128 * QST + 64 * QST + 128 * QST + 32 * VST2) * 4)

__global__ __launch_bounds__(256, 2) void flash_f16()
{
    extern __shared__ uint32_t smu[];
    uint32_t* Qs = smu;                  // [128][36]
    uint32_t* Ks = Qs + 128 * QST;       // [64][36]
    uint32_t* Ps = Ks + 64 * QST;        // [128][36]
    uint32_t* Vs = Ps + 128 * QST;       // [32][72]

    const int qt = blockIdx.x, h = blockIdx.y, b = blockIdx.z;
    const int tid = threadIdx.x, lane = tid & 31, w = tid >> 5;
    const int grp = lane >> 2, qid = lane & 3;

    const float* qbase = g_qkv + (size_t)b * L_SEQ * QKV_COLS + h * DH;
    const float* kbase = qbase + DIM;
    const float* vbase = qbase + 2 * DIM;

    const float QSCL = 0.125f * L2E;   // folded softmax scale (pre-rounding)

    // load Q tile: 128 rows, scaled, packed f16x2 along k
#pragma unroll
    for (int it = 0; it < 8; it++) {
        int idx = tid + it * 256;
        int r = idx >> 4, c4 = (idx & 15) << 2;
        float4 v = *(const float4*)(qbase + (size_t)(qt * 128 + r) * QKV_COLS + c4);
        *(uint2*)&Qs[r * QST + (c4 >> 1)] =
            make_uint2(pack_h2(v.x * QSCL, v.y * QSCL),
                       pack_h2(v.z * QSCL, v.w * QSCL));
    }

    const int rlo = w * 16 + grp;
    const float pq0 = g_pos[qt * 128 + rlo];
    const float pq1 = g_pos[qt * 128 + rlo + 8];

    float l0 = 0.0f, l1 = 0.0f;
    float o[8][4];
#pragma unroll
    for (int df = 0; df < 8; df++)
#pragma unroll
        for (int i = 0; i < 4; i++) o[df][i] = 0.0f;

    // K prefetch for tile 0 (rows of 64 f32; 4 float4/thread)
    float4 kreg[4];
    float2 vlo[4], vhi[4];
#pragma unroll
    for (int it = 0; it < 4; it++) {
        int idx = tid + it * 256;
        int r = idx >> 4, c4 = (idx & 15) << 2;
        kreg[it] = *(const float4*)(kbase + (size_t)r * QKV_COLS + c4);
    }
    __syncthreads();   // Qs visible before first S-phase

    for (int kt = 0; kt < L_SEQ / 64; kt++) {
        // store prefetched K (f16x2 along k); issue paired-row V loads
#pragma unroll
        for (int it = 0; it < 4; it++) {
            int idx = tid + it * 256;
            int r = idx >> 4, c4 = (idx & 15) << 2;
            float4 kv = kreg[it];
            *(uint2*)&Ks[r * QST + (c4 >> 1)] =
                make_uint2(pack_h2(kv.x, kv.y), pack_h2(kv.z, kv.w));
        }
#pragma unroll
        for (int it = 0; it < 4; it++) {
            int idx = tid + it * 256;
            int jp = idx >> 5, d2 = (idx & 31) << 1;
            const float* vrow = vbase + (size_t)(kt * 64 + 2 * jp) * QKV_COLS + d2;
            vlo[it] = *(const float2*)vrow;
            vhi[it] = *(const float2*)(vrow + QKV_COLS);
        }
        __syncthreads();   // Ks visible; all prev-iter PV Vs reads complete

        // S = Q @ K^T  (warp: 16 x 64), log2 units, fp16 k16 mma
        float s[8][4];
#pragma unroll
        for (int nf = 0; nf < 8; nf++)
#pragma unroll
            for (int i = 0; i < 4; i++) s[nf][i] = 0.0f;
#pragma unroll
        for (int kb = 0; kb < 4; kb++) {
            const int kk = kb * 8;     // u32 (k-pair) offset
            uint32_t a0 = Qs[rlo * QST + kk + qid];
            uint32_t a1 = Qs[(rlo + 8) * QST + kk + qid];
            uint32_t a2 = Qs[rlo * QST + kk + qid + 4];
            uint32_t a3 = Qs[(rlo + 8) * QST + kk + qid + 4];
#pragma unroll
            for (int nf = 0; nf < 8; nf++) {
                uint32_t b0 = Ks[(nf * 8 + grp) * QST + kk + qid];
                uint32_t b1 = Ks[(nf * 8 + grp) * QST + kk + qid + 4];
                mma16(s[nf], a0, a1, a2, a3, b0, b1);
            }
        }

        // p = 2^(s - |pq - pk|) via MUFU; accumulate sums; pack P (natural k-pairs)
#pragma unroll
        for (int nf = 0; nf < 8; nf++) {
            float pk0 = g_pos[kt * 64 + nf * 8 + 2 * qid];
            float pk1 = g_pos[kt * 64 + nf * 8 + 2 * qid + 1];
            float p00 = ex2_approx(s[nf][0] - fabsf(pq0 - pk0));
            float p01 = ex2_approx(s[nf][1] - fabsf(pq0 - pk1));
            float p10 = ex2_approx(s[nf][2] - fabsf(pq1 - pk0));
            float p11 = ex2_approx(s[nf][3] - fabsf(pq1 - pk1));
            l0 += p00 + p01; l1 += p10 + p11;
            Ps[rlo * QST + nf * 4 + qid]       = pack_h2(p00, p01);
            Ps[(rlo + 8) * QST + nf * 4 + qid] = pack_h2(p10, p11);
        }

        // store V (f16x2 along j, no transpose); prefetch next K
#pragma unroll
        for (int it = 0; it < 4; it++) {
            int idx = tid + it * 256;
            int jp = idx >> 5, d2 = (idx & 31) << 1;
            *(uint2*)&Vs[jp * VST2 + d2] =
                make_uint2(pack_h2(vlo[it].x, vhi[it].x),
                           pack_h2(vlo[it].y, vhi[it].y));
        }
        if (kt + 1 < L_SEQ / 64) {
#pragma unroll
            for (int it = 0; it < 4; it++) {
                int idx = tid + it * 256;
                int r = idx >> 4, c4 = (idx & 15) << 2;
                kreg[it] = *(const float4*)(kbase + (size_t)((kt + 1) * 64 + r) * QKV_COLS + c4);
            }
        }
        __syncthreads();   // Vs visible (Ps warp-private writes also done)

        // O += P @ V   (A = P warp rows, B = Vs j-pair layout)
#pragma unroll
        for (int kb = 0; kb < 4; kb++) {
            const int kk = kb * 8;     // j-pair offset
            uint32_t a0 = Ps[rlo * QST + kk + qid];
            uint32_t a1 = Ps[(rlo + 8) * QST + kk + qid];
            uint32_t a2 = Ps[rlo * QST + kk + qid + 4];
            uint32_t a3 = Ps[(rlo + 8) * QST + kk + qid + 4];
#pragma unroll
            for (int df = 0; df < 8; df++) {
                uint32_t b0 = Vs[(kk + qid) * VST2 + df * 8 + grp];
                uint32_t b1 = Vs[(kk + qid + 4) * VST2 + df * 8 + grp];
                mma16(o[df], a0, a1, a2, a3, b0, b1);
            }
        }
    }

    // epilogue: reduce row sums across the 4 qid lanes, normalize, store
    l0 += __shfl_xor_sync(0xffffffffu, l0, 1);
    l0 += __shfl_xor_sync(0xffffffffu, l0, 2);
    l1 += __shfl_xor_sync(0xffffffffu, l1, 1);
    l1 += __shfl_xor_sync(0xffffffffu, l1, 2);
    float inv0 = 1.0f / l0, inv1 = 1.0f / l1;
    float* obase = g_att + (size_t)b * L_SEQ * DIM + h * DH;
    int row = qt * 128 + rlo;
#pragma unroll
    for (int df = 0; df < 8; df++) {
        int cl = df * 8 + 2 * qid;
        *(float2*)(obase + (size_t)row * DIM + cl) =
            make_float2(o[df][0] * inv0, o[df][1] * inv0);
        *(float2*)(obase + (size_t)(row + 8) * DIM + cl) =
            make_float2(o[df][2] * inv1, o[df][3] * inv1);
    }
}

// ---------------------------------------------------------------------------
extern "C" void kernel_launch(void* const* d_in, const int* in_sizes, int n_in,
                              void* d_out, int out_size)
{
    const float* x      = (const float*)d_in[0];
    const float* w_qkv  = (const float*)d_in[1];
    const float* w_proj = (const float*)d_in[2];
    const float* b_proj = (const float*)d_in[3];
    float* out = (float*)d_out;

    float *qkv_ptr, *att_ptr;
    cudaGetSymbolAddress((void**)&qkv_ptr, g_qkv);
    cudaGetSymbolAddress((void**)&att_ptr, g_att);

    cudaFuncSetAttribute(flash_f16,
                         cudaFuncAttributeMaxDynamicSharedMemorySize, FLASH_SMEM16);

    const int M = BATCH * L_SEQ;  // 4096

    pos_init<<<L_SEQ / 256, 256>>>();

    gemm_tf32<<<dim3(QKV_COLS / 128, M / 128), 256>>>(
        x, w_qkv, qkv_ptr, M, QKV_COLS, DIM, nullptr);

    flash_f16<<<dim3(L_SEQ / 128, HEADS, BATCH), 256, FLASH_SMEM16>>>();

    gemm_tf32<<<dim3(DIM / 128, M / 128), 256>>>(
        att_ptr, w_proj, out, M, DIM, DIM, b_proj);
}